// round 11
// baseline (speedup 1.0000x reference)
#include <cuda_runtime.h>
#include <cuda_fp16.h>
#include <cstdint>
#include <math.h>

#define Bb 2
#define Tt 2048
#define TCc 512
#define Cc 1024
#define CCc 512
#define Hh 16
#define Dd 64

// ---------------------------------------------------------------------------
// Scratch (__device__ globals; no allocation allowed)
// ---------------------------------------------------------------------------
__device__ __half g_xh[Bb*Tt*Cc];
__device__ __half g_ch[Bb*TCc*CCc], g_cl[Bb*TCc*CCc];
__device__ __half g_yh[Bb*Tt*Cc];

// fused projection outputs: [B*T, 4096] = [q | k | v | qc], single fp16
__device__ __half g_qkvh[Bb*Tt*4*Cc];
// fused cross outputs: [B*TC, 2048] = [kc | vc], single fp16
__device__ __half g_kvch[Bb*TCc*2*Cc];

// fused transposed weights (single fp16)
__device__ __half g_W4_h[4*Cc*Cc];
__device__ __half g_W2_h[2*Cc*CCc];
__device__ __half g_Wp_h[Cc*Cc];
__device__ float g_b4[4*Cc], g_b2[2*Cc];

// ---------------------------------------------------------------------------
// helpers
// ---------------------------------------------------------------------------
__device__ __forceinline__ uint32_t smem_u32(const void* p) {
    uint32_t a;
    asm("{ .reg .u64 t; cvta.to.shared.u64 t, %1; cvt.u32.u64 %0, t; }"
        : "=r"(a) : "l"(p));
    return a;
}
__device__ __forceinline__ float ex2(float x) {
    float y; asm("ex2.approx.ftz.f32 %0, %1;" : "=f"(y) : "f"(x)); return y;
}

#define CP_ASYNC16(dst, src) \
    asm volatile("cp.async.cg.shared.global [%0], [%1], 16;" :: "r"(dst), "l"(src))
#define CP_COMMIT() asm volatile("cp.async.commit_group;" ::: "memory")
#define CP_WAIT0()  asm volatile("cp.async.wait_group 0;" ::: "memory")
#define CP_WAIT1()  asm volatile("cp.async.wait_group 1;" ::: "memory")

#define LDSM_X4(r0, r1, r2, r3, a) \
    asm volatile("ldmatrix.sync.aligned.m8n8.x4.shared.b16 {%0,%1,%2,%3}, [%4];" \
                 : "=r"(r0), "=r"(r1), "=r"(r2), "=r"(r3) : "r"(a))
#define LDSM_X4T(r0, r1, r2, r3, a) \
    asm volatile("ldmatrix.sync.aligned.m8n8.x4.trans.shared.b16 {%0,%1,%2,%3}, [%4];" \
                 : "=r"(r0), "=r"(r1), "=r"(r2), "=r"(r3) : "r"(a))

#define MMA_F16(d, a, b) \
    asm volatile("mma.sync.aligned.m16n8k16.row.col.f32.f16.f16.f32 " \
                 "{%0,%1,%2,%3}, {%4,%5,%6,%7}, {%8,%9}, {%0,%1,%2,%3};" \
                 : "+f"((d)[0]), "+f"((d)[1]), "+f"((d)[2]), "+f"((d)[3]) \
                 : "r"((a)[0]), "r"((a)[1]), "r"((a)[2]), "r"((a)[3]), \
                   "r"((b)[0]), "r"((b)[1]))

// ---------------------------------------------------------------------------
// prep kernels
// ---------------------------------------------------------------------------
__global__ void cvt_pair_kernel(const float* __restrict__ s, __half* __restrict__ h,
                                __half* __restrict__ l, int n)
{
    int i = blockIdx.x * blockDim.x + threadIdx.x;
    if (i < n) {
        float v = s[i];
        __half hh = __float2half(v);
        h[i] = hh;
        l[i] = __float2half(v - __half2float(hh));
    }
}

__global__ void cvt_single_kernel(const float* __restrict__ s, __half* __restrict__ h, int n)
{
    int i = blockIdx.x * blockDim.x + threadIdx.x;
    if (i < n) h[i] = __float2half(s[i]);
}

__global__ void transpose_all_kernel(
    const float* __restrict__ Wq,  const float* __restrict__ Wk,
    const float* __restrict__ Wv,  const float* __restrict__ Wcq,
    const float* __restrict__ Wck, const float* __restrict__ Wcv,
    const float* __restrict__ Wp)
{
    const int z = blockIdx.z;
    const float* W;
    __half* Th;
    int K;
    switch (z) {
        case 0: W = Wq;  Th = g_W4_h;               K = 1024; break;
        case 1: W = Wk;  Th = g_W4_h + 1024 * 1024; K = 1024; break;
        case 2: W = Wv;  Th = g_W4_h + 2048 * 1024; K = 1024; break;
        case 3: W = Wcq; Th = g_W4_h + 3072 * 1024; K = 1024; break;
        case 4: W = Wck; Th = g_W2_h;               K = 512;  break;
        case 5: W = Wcv; Th = g_W2_h + 1024 * 512;  K = 512;  break;
        default: W = Wp; Th = g_Wp_h;               K = 1024; break;
    }
    if (K == 512 && blockIdx.y >= 16) return;

    __shared__ float t[32][33];
    const int n0 = blockIdx.x * 32, k0 = blockIdx.y * 32;
    const int tx = threadIdx.x, ty = threadIdx.y;
    #pragma unroll
    for (int i = 0; i < 4; i++)
        t[ty + 8 * i][tx] = W[(size_t)(k0 + ty + 8 * i) * 1024 + n0 + tx];
    __syncthreads();
    #pragma unroll
    for (int i = 0; i < 4; i++) {
        float v = t[tx][ty + 8 * i];
        Th[(size_t)(n0 + ty + 8 * i) * K + k0 + tx] = __float2half(v);
    }
}

__global__ void bias_concat_kernel(
    const float* __restrict__ bq, const float* __restrict__ bk,
    const float* __restrict__ bv, const float* __restrict__ bcq,
    const float* __restrict__ bck, const float* __restrict__ bcv)
{
    int i = blockIdx.x * blockDim.x + threadIdx.x;
    if (i < 4096) {
        const float* s[4] = {bq, bk, bv, bcq};
        g_b4[i] = s[i >> 10][i & 1023];
    } else if (i < 6144) {
        int j = i - 4096;
        g_b2[j] = (j < 1024) ? bck[j] : bcv[j - 1024];
    }
}

// ---------------------------------------------------------------------------
// HMMA GEMM. TWO=true:  out = (Ah+Al) @ Bh^T + bias  (3 smem tiles/stage)
//            TWO=false: out = Ah @ Bh^T + bias       (2 smem tiles/stage)
// Output: fp32 (outf) OR single fp16 (outh).
// ---------------------------------------------------------------------------
#define BKg 32
#define LDAg 40
#define TILEB (128 * LDAg * 2)

template<bool TWO>
__global__ __launch_bounds__(256) void hmma_gemm_kernel(
    const __half* __restrict__ Ah, const __half* __restrict__ Al,
    const __half* __restrict__ Bh,
    const float* __restrict__ bias, float* __restrict__ outf,
    __half* __restrict__ outh,
    int M, int N, int K)
{
    constexpr int NT = TWO ? 3 : 2;
    constexpr int STG = NT * TILEB;

    extern __shared__ char smem[];
    const uint32_t sb = smem_u32(smem);
    const int tid = threadIdx.x;
    const int wid = tid >> 5, lane = tid & 31;
    const int bm = blockIdx.y * 128, bn = blockIdx.x * 128;

    const int wr = wid & 3;
    const int wc = wid >> 2;

    const char* gA  = (const char*)(Ah + (size_t)bm * K);
    const char* gAl = TWO ? (const char*)(Al + (size_t)bm * K) : nullptr;
    const char* gB  = (const char*)(Bh + (size_t)bn * K);

    const int row0 = tid >> 2, c16a = tid & 3;
    const int row1 = (tid + 256) >> 2;

    auto load_tile = [&](const char* g, uint32_t d, int kb) {
        g += (size_t)kb * (BKg * 2);
        CP_ASYNC16(d + row0 * (LDAg * 2) + c16a * 16,
                   g + (size_t)row0 * (K * 2) + c16a * 16);
        CP_ASYNC16(d + row1 * (LDAg * 2) + c16a * 16,
                   g + (size_t)row1 * (K * 2) + c16a * 16);
    };
    auto load_chunk = [&](int kb, int st) {
        const uint32_t sdst = sb + st * STG;
        load_tile(gA, sdst, kb);
        if (TWO) load_tile(gAl, sdst + TILEB, kb);
        load_tile(gB, sdst + (NT - 1) * TILEB, kb);
    };

    float acc[2][8][4] = {};

    const int nchunks = K / BKg;
    load_chunk(0, 0); CP_COMMIT();
    load_chunk(1, 1); CP_COMMIT();

    for (int kb = 0; kb < nchunks; kb++) {
        const int st = kb % 3;
        if (kb + 1 < nchunks) { CP_WAIT1(); } else { CP_WAIT0(); }
        __syncthreads();
        if (kb + 2 < nchunks) { load_chunk(kb + 2, (kb + 2) % 3); CP_COMMIT(); }

        const uint32_t ah = sb + st * STG;
        const uint32_t al = ah + TILEB;
        const uint32_t bh = ah + (NT - 1) * TILEB;

        #pragma unroll
        for (int ks = 0; ks < 2; ks++) {
            const int k0 = ks * 16;
            uint32_t Ahf[2][4], Alf[2][4], Bhf[8][2];

            #pragma unroll
            for (int mt = 0; mt < 2; mt++) {
                const int arow = wr * 32 + mt * 16 + (lane & 15);
                const int acol = k0 + (lane >> 4) * 8;
                const uint32_t ao = (uint32_t)(arow * LDAg + acol) * 2;
                LDSM_X4(Ahf[mt][0], Ahf[mt][1], Ahf[mt][2], Ahf[mt][3], ah + ao);
                if (TWO)
                    LDSM_X4(Alf[mt][0], Alf[mt][1], Alf[mt][2], Alf[mt][3], al + ao);
            }
            #pragma unroll
            for (int np = 0; np < 4; np++) {
                const int brow = wc * 64 + np * 16 + ((lane >> 4) & 1) * 8 + (lane & 7);
                const int bcol = k0 + ((lane >> 3) & 1) * 8;
                const uint32_t bo = (uint32_t)(brow * LDAg + bcol) * 2;
                LDSM_X4(Bhf[2*np][0], Bhf[2*np][1], Bhf[2*np+1][0], Bhf[2*np+1][1], bh + bo);
            }

            #pragma unroll
            for (int mt = 0; mt < 2; mt++)
                #pragma unroll
                for (int nt = 0; nt < 8; nt++) {
                    MMA_F16(acc[mt][nt], Ahf[mt], Bhf[nt]);
                    if (TWO) MMA_F16(acc[mt][nt], Alf[mt], Bhf[nt]);
                }
        }
    }

    const int crow = lane >> 2, ccol = (lane & 3) * 2;
    #pragma unroll
    for (int mt = 0; mt < 2; mt++) {
        #pragma unroll
        for (int hf2 = 0; hf2 < 2; hf2++) {
            const int r = bm + wr * 32 + mt * 16 + crow + hf2 * 8;
            #pragma unroll
            for (int nt = 0; nt < 8; nt++) {
                const int c = bn + wc * 64 + nt * 8 + ccol;
                float2 b2 = *(const float2*)&bias[c];
                float vx = acc[mt][nt][hf2 * 2 + 0] + b2.x;
                float vy = acc[mt][nt][hf2 * 2 + 1] + b2.y;
                if (outf) {
                    float2 v; v.x = vx; v.y = vy;
                    *(float2*)&outf[(size_t)r * N + c] = v;
                } else {
                    __half2 hh = __float22half2_rn(make_float2(vx, vy));
                    *(uint32_t*)&outh[(size_t)r * N + c] = *(uint32_t*)&hh;
                }
            }
        }
    }
}

// ---------------------------------------------------------------------------
// Fused HMMA flash attention (all single fp16 operands):
//   S = Qh Kh^T   (1 MMA/frag)
//   O += Ph Vh    (1 MMA/frag)
// phase 0 = causal self, phase 1 = cross. Self parked in smem fp32.
// ---------------------------------------------------------------------------
#define APB 144
#define QTILE (128 * APB)               // 18432
#define KVTILE (64 * APB)               // 9216
#define KVSTAGE (2 * KVTILE)            // 18432
#define SO_OFF (QTILE + 2 * KVSTAGE)    // 55296
#define ATT_SMEM (SO_OFF + 128 * 68 * 4)   // 90112

__global__ __launch_bounds__(256, 1) void attn_fused_kernel(
    const __half* __restrict__ qkvh,
    const __half* __restrict__ kvch, __half* __restrict__ Yh)
{
    extern __shared__ char smem[];
    const uint32_t sb = smem_u32(smem);
    float* sO = (float*)(smem + SO_OFF);
    const int tid = threadIdx.x, wid = tid >> 5, lane = tid & 31;
    const int qt = gridDim.x - 1 - blockIdx.x;   // heavy first
    const int h = blockIdx.y, b = blockIdx.z;
    const int q0 = qt * 128;

    const uint32_t sQh = sb;
    const uint32_t sKV = sb + QTILE;

    const int crow = lane >> 2, ccol = (lane & 3) * 2;
    const int rloc = wid * 16 + crow;
    const int wrow = q0 + wid * 16;
    const float cs = 0.125f * 1.44269504089f;

    for (int phase = 0; phase < 2; phase++) {
        const bool causal = (phase == 0);
        const int ldq  = 4 * Cc;
        const int ldkv = causal ? 4 * Cc : 2 * Cc;
        const int ntt  = causal ? (2 * qt + 2) : (TCc / 64);

        const __half* Qhp = causal ? qkvh        : qkvh + 3072;
        const __half* Khp = causal ? qkvh + 1024 : kvch;
        const __half* Vhp = causal ? qkvh + 2048 : kvch + 1024;

        const size_t qoff = ((size_t)b * Tt + q0) * ldq + h * Dd;
        const size_t koff = ((size_t)b * (causal ? Tt : TCc)) * ldkv + h * Dd;

        // ---- load Q ----
        {
            const char* gq = (const char*)(Qhp + qoff);
            #pragma unroll
            for (int it = 0; it < 4; it++) {
                int idx = it * 256 + tid;
                int r = idx >> 3, c = idx & 7;
                CP_ASYNC16(sQh + r * APB + c * 16,
                           gq + (size_t)r * (ldq * 2) + c * 16);
            }
        }
        CP_COMMIT();

        const char* gk[2] = { (const char*)(Khp + koff), (const char*)(Vhp + koff) };
        auto load_kv = [&](int kt, int st) {
            uint32_t dst = sKV + st * KVSTAGE;
            #pragma unroll
            for (int m = 0; m < 2; m++) {
                #pragma unroll
                for (int it = 0; it < 2; it++) {
                    int idx = it * 256 + tid;
                    int r = idx >> 3, c = idx & 7;
                    CP_ASYNC16(dst + m * KVTILE + r * APB + c * 16,
                               gk[m] + ((size_t)(kt * 64 + r)) * (ldkv * 2) + c * 16);
                }
            }
        };

        load_kv(0, 0);
        CP_COMMIT();
        CP_WAIT1();
        __syncthreads();

        uint32_t Qhf[4][4];
        {
            const int r = wid * 16 + (lane & 7) + 8 * ((lane >> 3) & 1);
            const int cb = 8 * (lane >> 4);
            #pragma unroll
            for (int kc = 0; kc < 4; kc++) {
                const uint32_t off = (uint32_t)r * APB + (kc * 16 + cb) * 2;
                LDSM_X4(Qhf[kc][0], Qhf[kc][1], Qhf[kc][2], Qhf[kc][3], sQh + off);
            }
        }

        float o[8][4] = {};
        float m0 = -1e30f, m1 = -1e30f, l0 = 0.f, l1 = 0.f;

        for (int kt = 0; kt < ntt; kt++) {
            const int st = kt & 1;
            if (kt + 1 < ntt) { load_kv(kt + 1, st ^ 1); CP_COMMIT(); CP_WAIT1(); }
            else              { CP_WAIT0(); }
            __syncthreads();

            const int k0 = kt * 64;
            const bool active = !causal || (k0 <= wrow + 15);
            if (active) {
                const uint32_t sKhT = sKV + st * KVSTAGE;
                const uint32_t sVhT = sKhT + KVTILE;

                // ---- S = Qh Kh^T ----
                float s[8][4] = {};
                {
                    const int krow = (lane & 7) + 8 * (lane >> 4);
                    const int kcolb = 8 * ((lane >> 3) & 1);
                    #pragma unroll
                    for (int kc = 0; kc < 4; kc++) {
                        uint32_t bh[8][2];
                        #pragma unroll
                        for (int np = 0; np < 4; np++) {
                            const uint32_t off =
                                (uint32_t)(np * 16 + krow) * APB + (kc * 16 + kcolb) * 2;
                            LDSM_X4(bh[2*np][0], bh[2*np][1], bh[2*np+1][0], bh[2*np+1][1],
                                    sKhT + off);
                        }
                        #pragma unroll
                        for (int nt = 0; nt < 8; nt++)
                            MMA_F16(s[nt], Qhf[kc], bh[nt]);
                    }
                }

                const bool dm = causal && (k0 + 63 > wrow);
                float zx0 = -1e30f, zx1 = -1e30f;
                #pragma unroll
                for (int nt = 0; nt < 8; nt++) {
                    #pragma unroll
                    for (int r = 0; r < 4; r++) {
                        float z = s[nt][r] * cs;
                        if (dm) {
                            const int col = k0 + nt * 8 + ccol + (r & 1);
                            const int row = wrow + crow + 8 * (r >> 1);
                            if (col > row) z = -1e30f;
                        }
                        s[nt][r] = z;
                    }
                    zx0 = fmaxf(zx0, fmaxf(s[nt][0], s[nt][1]));
                    zx1 = fmaxf(zx1, fmaxf(s[nt][2], s[nt][3]));
                }
                zx0 = fmaxf(zx0, __shfl_xor_sync(0xffffffffu, zx0, 1));
                zx0 = fmaxf(zx0, __shfl_xor_sync(0xffffffffu, zx0, 2));
                zx1 = fmaxf(zx1, __shfl_xor_sync(0xffffffffu, zx1, 1));
                zx1 = fmaxf(zx1, __shfl_xor_sync(0xffffffffu, zx1, 2));
                const float mn0 = fmaxf(m0, zx0), mn1 = fmaxf(m1, zx1);
                const float a0 = ex2(m0 - mn0), a1 = ex2(m1 - mn1);
                m0 = mn0; m1 = mn1;

                float ps0 = 0.f, ps1 = 0.f;
                uint32_t pah[4][4];
                #pragma unroll
                for (int nt = 0; nt < 8; nt++) {
                    const float p0 = ex2(s[nt][0] - mn0), p1 = ex2(s[nt][1] - mn0);
                    const float p2 = ex2(s[nt][2] - mn1), p3 = ex2(s[nt][3] - mn1);
                    ps0 += p0 + p1; ps1 += p2 + p3;
                    __half2 h01 = __float22half2_rn(make_float2(p0, p1));
                    __half2 h23 = __float22half2_rn(make_float2(p2, p3));
                    pah[nt >> 1][(nt & 1) * 2 + 0] = *(uint32_t*)&h01;
                    pah[nt >> 1][(nt & 1) * 2 + 1] = *(uint32_t*)&h23;
                }
                l0 = l0 * a0 + ps0;
                l1 = l1 * a1 + ps1;
                #pragma unroll
                for (int nt = 0; nt < 8; nt++) {
                    o[nt][0] *= a0; o[nt][1] *= a0;
                    o[nt][2] *= a1; o[nt][3] *= a1;
                }

                // ---- O += Ph Vh ----
                {
                    const int vrl = (lane & 7) + 8 * ((lane >> 3) & 1);
                    const int vcb = 8 * (lane >> 4);
                    #pragma unroll
                    for (int kc = 0; kc < 4; kc++) {
                        uint32_t vh[8][2];
                        #pragma unroll
                        for (int dp = 0; dp < 4; dp++) {
                            const uint32_t off =
                                (uint32_t)(kc * 16 + vrl) * APB + (dp * 16 + vcb) * 2;
                            LDSM_X4T(vh[2*dp][0], vh[2*dp][1], vh[2*dp+1][0], vh[2*dp+1][1],
                                     sVhT + off);
                        }
                        #pragma unroll
                        for (int nt = 0; nt < 8; nt++)
                            MMA_F16(o[nt], pah[kc], vh[nt]);
                    }
                }
            }
            __syncthreads();
        }

        l0 += __shfl_xor_sync(0xffffffffu, l0, 1);
        l0 += __shfl_xor_sync(0xffffffffu, l0, 2);
        l1 += __shfl_xor_sync(0xffffffffu, l1, 1);
        l1 += __shfl_xor_sync(0xffffffffu, l1, 2);
        const float i0 = 1.f / l0, i1 = 1.f / l1;

        if (phase == 0) {
            #pragma unroll
            for (int nt = 0; nt < 8; nt++) {
                const int c = nt * 8 + ccol;
                sO[rloc * 68 + c]           = o[nt][0] * i0;
                sO[rloc * 68 + c + 1]       = o[nt][1] * i0;
                sO[(rloc + 8) * 68 + c]     = o[nt][2] * i1;
                sO[(rloc + 8) * 68 + c + 1] = o[nt][3] * i1;
            }
        } else {
            const int r0 = q0 + wid * 16 + crow;
            __half* yh0 = Yh + ((size_t)b * Tt + r0) * Cc + h * Dd;
            __half* yh1 = yh0 + 8 * Cc;
            #pragma unroll
            for (int nt = 0; nt < 8; nt++) {
                const int c = nt * 8 + ccol;
                float vx0 = sO[rloc * 68 + c]           + o[nt][0] * i0;
                float vy0 = sO[rloc * 68 + c + 1]       + o[nt][1] * i0;
                float vx1 = sO[(rloc + 8) * 68 + c]     + o[nt][2] * i1;
                float vy1 = sO[(rloc + 8) * 68 + c + 1] + o[nt][3] * i1;
                __half2 h0 = __float22half2_rn(make_float2(vx0, vy0));
                __half2 h1 = __float22half2_rn(make_float2(vx1, vy1));
                *(uint32_t*)&yh0[c] = *(uint32_t*)&h0;
                *(uint32_t*)&yh1[c] = *(uint32_t*)&h1;
            }
        }
    }
}

// ---------------------------------------------------------------------------

extern "C" void kernel_launch(void* const* d_in, const int* in_sizes, int n_in,
                              void* d_out, int out_size)
{
    const float* x     = (const float*)d_in[0];
    const float* cross = (const float*)d_in[1];
    const float* Wk  = (const float*)d_in[2];   const float* bk  = (const float*)d_in[3];
    const float* Wq  = (const float*)d_in[4];   const float* bq  = (const float*)d_in[5];
    const float* Wv  = (const float*)d_in[6];   const float* bv  = (const float*)d_in[7];
    const float* Wck = (const float*)d_in[8];   const float* bck = (const float*)d_in[9];
    const float* Wcq = (const float*)d_in[10];  const float* bcq = (const float*)d_in[11];
    const float* Wcv = (const float*)d_in[12];  const float* bcv = (const float*)d_in[13];
    const float* Wp  = (const float*)d_in[14];  const float* bp  = (const float*)d_in[15];
    float* out = (float*)d_out;

    __half *xh, *ch, *cl, *yh;
    cudaGetSymbolAddress((void**)&xh, g_xh);
    cudaGetSymbolAddress((void**)&ch, g_ch); cudaGetSymbolAddress((void**)&cl, g_cl);
    cudaGetSymbolAddress((void**)&yh, g_yh);

    __half *qkvh, *kvch;
    cudaGetSymbolAddress((void**)&qkvh, g_qkvh);
    cudaGetSymbolAddress((void**)&kvch, g_kvch);

    __half *w4h, *w2h, *wph;
    cudaGetSymbolAddress((void**)&w4h, g_W4_h);
    cudaGetSymbolAddress((void**)&w2h, g_W2_h);
    cudaGetSymbolAddress((void**)&wph, g_Wp_h);
    float *b4, *b2;
    cudaGetSymbolAddress((void**)&b4, g_b4); cudaGetSymbolAddress((void**)&b2, g_b2);

    // prep
    transpose_all_kernel<<<dim3(32, 32, 7), dim3(32, 8)>>>(Wq, Wk, Wv, Wcq, Wck, Wcv, Wp);
    bias_concat_kernel<<<24, 256>>>(bq, bk, bv, bcq, bck, bcv);
    const int nx = Bb * Tt * Cc, nc = Bb * TCc * CCc;
    cvt_single_kernel<<<(nx + 255) / 256, 256>>>(x, xh, nx);
    cvt_pair_kernel<<<(nc + 255) / 256, 256>>>(cross, ch, cl, nc);

    const int SM1 = 3 * 2 * TILEB;   // 1-term GEMM smem (61440)
    const int SM2 = 3 * 3 * TILEB;   // 2-term GEMM smem (92160)
    cudaFuncSetAttribute(hmma_gemm_kernel<false>,
                         cudaFuncAttributeMaxDynamicSharedMemorySize, SM1);
    cudaFuncSetAttribute(hmma_gemm_kernel<true>,
                         cudaFuncAttributeMaxDynamicSharedMemorySize, SM2);
    const dim3 gblk(256);

    // QKV projection: single x @ single W4 -> single qkv
    hmma_gemm_kernel<false><<<dim3(32, 32), gblk, SM1>>>(
        xh, nullptr, w4h, b4, nullptr, qkvh, Bb*Tt, 4*Cc, Cc);
    // cross projection: (ch+cl) @ single W2 -> single kvc
    hmma_gemm_kernel<true><<<dim3(16, 8), gblk, SM2>>>(
        ch, cl, w2h, b2, nullptr, kvch, Bb*TCc, 2*Cc, CCc);

    cudaFuncSetAttribute(attn_fused_kernel, cudaFuncAttributeMaxDynamicSharedMemorySize, ATT_SMEM);
    attn_fused_kernel<<<dim3(Tt / 128, Hh, Bb), gblk, ATT_SMEM>>>(
        qkvh, kvch, yh);

    // output projection: single y @ single Wp -> fp32 out
    hmma_gemm_kernel<false><<<dim3(8, 32), gblk, SM1>>>(
        yh, nullptr, wph, bp, out, nullptr, Bb*Tt, Cc, Cc);
}

// round 12
// speedup vs baseline: 1.0017x; 1.0017x over previous
#include <cuda_runtime.h>
#include <cuda_fp16.h>
#include <cstdint>
#include <math.h>

#define Bb 2
#define Tt 2048
#define TCc 512
#define Cc 1024
#define CCc 512
#define Hh 16
#define Dd 64

// ---------------------------------------------------------------------------
// Scratch (__device__ globals; no allocation allowed)
// ---------------------------------------------------------------------------
__device__ __half g_xh[Bb*Tt*Cc];
__device__ __half g_ch[Bb*TCc*CCc], g_cl[Bb*TCc*CCc];
__device__ __half g_yh[Bb*Tt*Cc];

// fused projection outputs: [B*T, 4096] = [q | k | v | qc], single fp16
__device__ __half g_qkvh[Bb*Tt*4*Cc];
// fused cross outputs: [B*TC, 2048] = [kc | vc], single fp16
__device__ __half g_kvch[Bb*TCc*2*Cc];

// fused transposed weights (single fp16)
__device__ __half g_W4_h[4*Cc*Cc];
__device__ __half g_W2_h[2*Cc*CCc];
__device__ __half g_Wp_h[Cc*Cc];
__device__ float g_b4[4*Cc], g_b2[2*Cc];

// ---------------------------------------------------------------------------
// helpers
// ---------------------------------------------------------------------------
__device__ __forceinline__ uint32_t smem_u32(const void* p) {
    uint32_t a;
    asm("{ .reg .u64 t; cvta.to.shared.u64 t, %1; cvt.u32.u64 %0, t; }"
        : "=r"(a) : "l"(p));
    return a;
}
__device__ __forceinline__ float ex2(float x) {
    float y; asm("ex2.approx.ftz.f32 %0, %1;" : "=f"(y) : "f"(x)); return y;
}

#define CP_ASYNC16(dst, src) \
    asm volatile("cp.async.cg.shared.global [%0], [%1], 16;" :: "r"(dst), "l"(src))
#define CP_COMMIT() asm volatile("cp.async.commit_group;" ::: "memory")
#define CP_WAIT0()  asm volatile("cp.async.wait_group 0;" ::: "memory")
#define CP_WAIT1()  asm volatile("cp.async.wait_group 1;" ::: "memory")

#define LDSM_X4(r0, r1, r2, r3, a) \
    asm volatile("ldmatrix.sync.aligned.m8n8.x4.shared.b16 {%0,%1,%2,%3}, [%4];" \
                 : "=r"(r0), "=r"(r1), "=r"(r2), "=r"(r3) : "r"(a))
#define LDSM_X4T(r0, r1, r2, r3, a) \
    asm volatile("ldmatrix.sync.aligned.m8n8.x4.trans.shared.b16 {%0,%1,%2,%3}, [%4];" \
                 : "=r"(r0), "=r"(r1), "=r"(r2), "=r"(r3) : "r"(a))

#define MMA_F16(d, a, b) \
    asm volatile("mma.sync.aligned.m16n8k16.row.col.f32.f16.f16.f32 " \
                 "{%0,%1,%2,%3}, {%4,%5,%6,%7}, {%8,%9}, {%0,%1,%2,%3};" \
                 : "+f"((d)[0]), "+f"((d)[1]), "+f"((d)[2]), "+f"((d)[3]) \
                 : "r"((a)[0]), "r"((a)[1]), "r"((a)[2]), "r"((a)[3]), \
                   "r"((b)[0]), "r"((b)[1]))

// ---------------------------------------------------------------------------
// prep kernels
// ---------------------------------------------------------------------------
__global__ void cvt_pair_kernel(const float* __restrict__ s, __half* __restrict__ h,
                                __half* __restrict__ l, int n)
{
    int i = blockIdx.x * blockDim.x + threadIdx.x;
    if (i < n) {
        float v = s[i];
        __half hh = __float2half(v);
        h[i] = hh;
        l[i] = __float2half(v - __half2float(hh));
    }
}

__global__ void cvt_single_kernel(const float* __restrict__ s, __half* __restrict__ h, int n)
{
    int i = blockIdx.x * blockDim.x + threadIdx.x;
    if (i < n) h[i] = __float2half(s[i]);
}

__global__ void transpose_all_kernel(
    const float* __restrict__ Wq,  const float* __restrict__ Wk,
    const float* __restrict__ Wv,  const float* __restrict__ Wcq,
    const float* __restrict__ Wck, const float* __restrict__ Wcv,
    const float* __restrict__ Wp)
{
    const int z = blockIdx.z;
    const float* W;
    __half* Th;
    int K;
    switch (z) {
        case 0: W = Wq;  Th = g_W4_h;               K = 1024; break;
        case 1: W = Wk;  Th = g_W4_h + 1024 * 1024; K = 1024; break;
        case 2: W = Wv;  Th = g_W4_h + 2048 * 1024; K = 1024; break;
        case 3: W = Wcq; Th = g_W4_h + 3072 * 1024; K = 1024; break;
        case 4: W = Wck; Th = g_W2_h;               K = 512;  break;
        case 5: W = Wcv; Th = g_W2_h + 1024 * 512;  K = 512;  break;
        default: W = Wp; Th = g_Wp_h;               K = 1024; break;
    }
    if (K == 512 && blockIdx.y >= 16) return;

    __shared__ float t[32][33];
    const int n0 = blockIdx.x * 32, k0 = blockIdx.y * 32;
    const int tx = threadIdx.x, ty = threadIdx.y;
    #pragma unroll
    for (int i = 0; i < 4; i++)
        t[ty + 8 * i][tx] = W[(size_t)(k0 + ty + 8 * i) * 1024 + n0 + tx];
    __syncthreads();
    #pragma unroll
    for (int i = 0; i < 4; i++) {
        float v = t[tx][ty + 8 * i];
        Th[(size_t)(n0 + ty + 8 * i) * K + k0 + tx] = __float2half(v);
    }
}

__global__ void bias_concat_kernel(
    const float* __restrict__ bq, const float* __restrict__ bk,
    const float* __restrict__ bv, const float* __restrict__ bcq,
    const float* __restrict__ bck, const float* __restrict__ bcv)
{
    int i = blockIdx.x * blockDim.x + threadIdx.x;
    if (i < 4096) {
        const float* s[4] = {bq, bk, bv, bcq};
        g_b4[i] = s[i >> 10][i & 1023];
    } else if (i < 6144) {
        int j = i - 4096;
        g_b2[j] = (j < 1024) ? bck[j] : bcv[j - 1024];
    }
}

// ---------------------------------------------------------------------------
// HMMA GEMM. TWO=true:  out = (Ah+Al) @ Bh^T + bias  (3 smem tiles/stage)
//            TWO=false: out = Ah @ Bh^T + bias       (2 smem tiles/stage)
// Output: fp32 (outf) OR single fp16 (outh).
// ---------------------------------------------------------------------------
#define BKg 32
#define LDAg 40
#define TILEB (128 * LDAg * 2)

template<bool TWO>
__global__ __launch_bounds__(256) void hmma_gemm_kernel(
    const __half* __restrict__ Ah, const __half* __restrict__ Al,
    const __half* __restrict__ Bh,
    const float* __restrict__ bias, float* __restrict__ outf,
    __half* __restrict__ outh,
    int M, int N, int K)
{
    constexpr int NT = TWO ? 3 : 2;
    constexpr int STG = NT * TILEB;

    extern __shared__ char smem[];
    const uint32_t sb = smem_u32(smem);
    const int tid = threadIdx.x;
    const int wid = tid >> 5, lane = tid & 31;
    const int bm = blockIdx.y * 128, bn = blockIdx.x * 128;

    const int wr = wid & 3;
    const int wc = wid >> 2;

    const char* gA  = (const char*)(Ah + (size_t)bm * K);
    const char* gAl = TWO ? (const char*)(Al + (size_t)bm * K) : nullptr;
    const char* gB  = (const char*)(Bh + (size_t)bn * K);

    const int row0 = tid >> 2, c16a = tid & 3;
    const int row1 = (tid + 256) >> 2;

    auto load_tile = [&](const char* g, uint32_t d, int kb) {
        g += (size_t)kb * (BKg * 2);
        CP_ASYNC16(d + row0 * (LDAg * 2) + c16a * 16,
                   g + (size_t)row0 * (K * 2) + c16a * 16);
        CP_ASYNC16(d + row1 * (LDAg * 2) + c16a * 16,
                   g + (size_t)row1 * (K * 2) + c16a * 16);
    };
    auto load_chunk = [&](int kb, int st) {
        const uint32_t sdst = sb + st * STG;
        load_tile(gA, sdst, kb);
        if (TWO) load_tile(gAl, sdst + TILEB, kb);
        load_tile(gB, sdst + (NT - 1) * TILEB, kb);
    };

    float acc[2][8][4] = {};

    const int nchunks = K / BKg;
    load_chunk(0, 0); CP_COMMIT();
    load_chunk(1, 1); CP_COMMIT();

    for (int kb = 0; kb < nchunks; kb++) {
        const int st = kb % 3;
        if (kb + 1 < nchunks) { CP_WAIT1(); } else { CP_WAIT0(); }
        __syncthreads();
        if (kb + 2 < nchunks) { load_chunk(kb + 2, (kb + 2) % 3); CP_COMMIT(); }

        const uint32_t ah = sb + st * STG;
        const uint32_t al = ah + TILEB;
        const uint32_t bh = ah + (NT - 1) * TILEB;

        #pragma unroll
        for (int ks = 0; ks < 2; ks++) {
            const int k0 = ks * 16;
            uint32_t Ahf[2][4], Alf[2][4], Bhf[8][2];

            #pragma unroll
            for (int mt = 0; mt < 2; mt++) {
                const int arow = wr * 32 + mt * 16 + (lane & 15);
                const int acol = k0 + (lane >> 4) * 8;
                const uint32_t ao = (uint32_t)(arow * LDAg + acol) * 2;
                LDSM_X4(Ahf[mt][0], Ahf[mt][1], Ahf[mt][2], Ahf[mt][3], ah + ao);
                if (TWO)
                    LDSM_X4(Alf[mt][0], Alf[mt][1], Alf[mt][2], Alf[mt][3], al + ao);
            }
            #pragma unroll
            for (int np = 0; np < 4; np++) {
                const int brow = wc * 64 + np * 16 + ((lane >> 4) & 1) * 8 + (lane & 7);
                const int bcol = k0 + ((lane >> 3) & 1) * 8;
                const uint32_t bo = (uint32_t)(brow * LDAg + bcol) * 2;
                LDSM_X4(Bhf[2*np][0], Bhf[2*np][1], Bhf[2*np+1][0], Bhf[2*np+1][1], bh + bo);
            }

            #pragma unroll
            for (int mt = 0; mt < 2; mt++)
                #pragma unroll
                for (int nt = 0; nt < 8; nt++) {
                    MMA_F16(acc[mt][nt], Ahf[mt], Bhf[nt]);
                    if (TWO) MMA_F16(acc[mt][nt], Alf[mt], Bhf[nt]);
                }
        }
    }

    const int crow = lane >> 2, ccol = (lane & 3) * 2;
    #pragma unroll
    for (int mt = 0; mt < 2; mt++) {
        #pragma unroll
        for (int hf2 = 0; hf2 < 2; hf2++) {
            const int r = bm + wr * 32 + mt * 16 + crow + hf2 * 8;
            #pragma unroll
            for (int nt = 0; nt < 8; nt++) {
                const int c = bn + wc * 64 + nt * 8 + ccol;
                float2 b2 = *(const float2*)&bias[c];
                float vx = acc[mt][nt][hf2 * 2 + 0] + b2.x;
                float vy = acc[mt][nt][hf2 * 2 + 1] + b2.y;
                if (outf) {
                    float2 v; v.x = vx; v.y = vy;
                    *(float2*)&outf[(size_t)r * N + c] = v;
                } else {
                    __half2 hh = __float22half2_rn(make_float2(vx, vy));
                    *(uint32_t*)&outh[(size_t)r * N + c] = *(uint32_t*)&hh;
                }
            }
        }
    }
}

// ---------------------------------------------------------------------------
// Fused HMMA flash attention (all single fp16 operands):
//   S = Qh Kh^T   (1 MMA/frag)
//   O += Ph Vh    (1 MMA/frag)
// phase 0 = causal self, phase 1 = cross. Self parked in smem fp32.
// ---------------------------------------------------------------------------
#define APB 144
#define QTILE (128 * APB)               // 18432
#define KVTILE (64 * APB)               // 9216
#define KVSTAGE (2 * KVTILE)            // 18432
#define SO_OFF (QTILE + 2 * KVSTAGE)    // 55296
#define ATT_SMEM (SO_OFF + 128 * 68 * 4)   // 90112

__global__ __launch_bounds__(256, 1) void attn_fused_kernel(
    const __half* __restrict__ qkvh,
    const __half* __restrict__ kvch, __half* __restrict__ Yh)
{
    extern __shared__ char smem[];
    const uint32_t sb = smem_u32(smem);
    float* sO = (float*)(smem + SO_OFF);
    const int tid = threadIdx.x, wid = tid >> 5, lane = tid & 31;
    const int qt = gridDim.x - 1 - blockIdx.x;   // heavy first
    const int h = blockIdx.y, b = blockIdx.z;
    const int q0 = qt * 128;

    const uint32_t sQh = sb;
    const uint32_t sKV = sb + QTILE;

    const int crow = lane >> 2, ccol = (lane & 3) * 2;
    const int rloc = wid * 16 + crow;
    const int wrow = q0 + wid * 16;
    const float cs = 0.125f * 1.44269504089f;

    for (int phase = 0; phase < 2; phase++) {
        const bool causal = (phase == 0);
        const int ldq  = 4 * Cc;
        const int ldkv = causal ? 4 * Cc : 2 * Cc;
        const int ntt  = causal ? (2 * qt + 2) : (TCc / 64);

        const __half* Qhp = causal ? qkvh        : qkvh + 3072;
        const __half* Khp = causal ? qkvh + 1024 : kvch;
        const __half* Vhp = causal ? qkvh + 2048 : kvch + 1024;

        const size_t qoff = ((size_t)b * Tt + q0) * ldq + h * Dd;
        const size_t koff = ((size_t)b * (causal ? Tt : TCc)) * ldkv + h * Dd;

        // ---- load Q ----
        {
            const char* gq = (const char*)(Qhp + qoff);
            #pragma unroll
            for (int it = 0; it < 4; it++) {
                int idx = it * 256 + tid;
                int r = idx >> 3, c = idx & 7;
                CP_ASYNC16(sQh + r * APB + c * 16,
                           gq + (size_t)r * (ldq * 2) + c * 16);
            }
        }
        CP_COMMIT();

        const char* gk[2] = { (const char*)(Khp + koff), (const char*)(Vhp + koff) };
        auto load_kv = [&](int kt, int st) {
            uint32_t dst = sKV + st * KVSTAGE;
            #pragma unroll
            for (int m = 0; m < 2; m++) {
                #pragma unroll
                for (int it = 0; it < 2; it++) {
                    int idx = it * 256 + tid;
                    int r = idx >> 3, c = idx & 7;
                    CP_ASYNC16(dst + m * KVTILE + r * APB + c * 16,
                               gk[m] + ((size_t)(kt * 64 + r)) * (ldkv * 2) + c * 16);
                }
            }
        };

        load_kv(0, 0);
        CP_COMMIT();
        CP_WAIT1();
        __syncthreads();

        uint32_t Qhf[4][4];
        {
            const int r = wid * 16 + (lane & 7) + 8 * ((lane >> 3) & 1);
            const int cb = 8 * (lane >> 4);
            #pragma unroll
            for (int kc = 0; kc < 4; kc++) {
                const uint32_t off = (uint32_t)r * APB + (kc * 16 + cb) * 2;
                LDSM_X4(Qhf[kc][0], Qhf[kc][1], Qhf[kc][2], Qhf[kc][3], sQh + off);
            }
        }

        float o[8][4] = {};
        float m0 = -1e30f, m1 = -1e30f, l0 = 0.f, l1 = 0.f;

        for (int kt = 0; kt < ntt; kt++) {
            const int st = kt & 1;
            if (kt + 1 < ntt) { load_kv(kt + 1, st ^ 1); CP_COMMIT(); CP_WAIT1(); }
            else              { CP_WAIT0(); }
            __syncthreads();

            const int k0 = kt * 64;
            const bool active = !causal || (k0 <= wrow + 15);
            if (active) {
                const uint32_t sKhT = sKV + st * KVSTAGE;
                const uint32_t sVhT = sKhT + KVTILE;

                // ---- S = Qh Kh^T ----
                float s[8][4] = {};
                {
                    const int krow = (lane & 7) + 8 * (lane >> 4);
                    const int kcolb = 8 * ((lane >> 3) & 1);
                    #pragma unroll
                    for (int kc = 0; kc < 4; kc++) {
                        uint32_t bh[8][2];
                        #pragma unroll
                        for (int np = 0; np < 4; np++) {
                            const uint32_t off =
                                (uint32_t)(np * 16 + krow) * APB + (kc * 16 + kcolb) * 2;
                            LDSM_X4(bh[2*np][0], bh[2*np][1], bh[2*np+1][0], bh[2*np+1][1],
                                    sKhT + off);
                        }
                        #pragma unroll
                        for (int nt = 0; nt < 8; nt++)
                            MMA_F16(s[nt], Qhf[kc], bh[nt]);
                    }
                }

                const bool dm = causal && (k0 + 63 > wrow);
                float zx0 = -1e30f, zx1 = -1e30f;
                #pragma unroll
                for (int nt = 0; nt < 8; nt++) {
                    #pragma unroll
                    for (int r = 0; r < 4; r++) {
                        float z = s[nt][r] * cs;
                        if (dm) {
                            const int col = k0 + nt * 8 + ccol + (r & 1);
                            const int row = wrow + crow + 8 * (r >> 1);
                            if (col > row) z = -1e30f;
                        }
                        s[nt][r] = z;
                    }
                    zx0 = fmaxf(zx0, fmaxf(s[nt][0], s[nt][1]));
                    zx1 = fmaxf(zx1, fmaxf(s[nt][2], s[nt][3]));
                }
                zx0 = fmaxf(zx0, __shfl_xor_sync(0xffffffffu, zx0, 1));
                zx0 = fmaxf(zx0, __shfl_xor_sync(0xffffffffu, zx0, 2));
                zx1 = fmaxf(zx1, __shfl_xor_sync(0xffffffffu, zx1, 1));
                zx1 = fmaxf(zx1, __shfl_xor_sync(0xffffffffu, zx1, 2));
                const float mn0 = fmaxf(m0, zx0), mn1 = fmaxf(m1, zx1);
                const float a0 = ex2(m0 - mn0), a1 = ex2(m1 - mn1);
                m0 = mn0; m1 = mn1;

                float ps0 = 0.f, ps1 = 0.f;
                uint32_t pah[4][4];
                #pragma unroll
                for (int nt = 0; nt < 8; nt++) {
                    const float p0 = ex2(s[nt][0] - mn0), p1 = ex2(s[nt][1] - mn0);
                    const float p2 = ex2(s[nt][2] - mn1), p3 = ex2(s[nt][3] - mn1);
                    ps0 += p0 + p1; ps1 += p2 + p3;
                    __half2 h01 = __float22half2_rn(make_float2(p0, p1));
                    __half2 h23 = __float22half2_rn(make_float2(p2, p3));
                    pah[nt >> 1][(nt & 1) * 2 + 0] = *(uint32_t*)&h01;
                    pah[nt >> 1][(nt & 1) * 2 + 1] = *(uint32_t*)&h23;
                }
                l0 = l0 * a0 + ps0;
                l1 = l1 * a1 + ps1;
                #pragma unroll
                for (int nt = 0; nt < 8; nt++) {
                    o[nt][0] *= a0; o[nt][1] *= a0;
                    o[nt][2] *= a1; o[nt][3] *= a1;
                }

                // ---- O += Ph Vh ----
                {
                    const int vrl = (lane & 7) + 8 * ((lane >> 3) & 1);
                    const int vcb = 8 * (lane >> 4);
                    #pragma unroll
                    for (int kc = 0; kc < 4; kc++) {
                        uint32_t vh[8][2];
                        #pragma unroll
                        for (int dp = 0; dp < 4; dp++) {
                            const uint32_t off =
                                (uint32_t)(kc * 16 + vrl) * APB + (dp * 16 + vcb) * 2;
                            LDSM_X4T(vh[2*dp][0], vh[2*dp][1], vh[2*dp+1][0], vh[2*dp+1][1],
                                     sVhT + off);
                        }
                        #pragma unroll
                        for (int nt = 0; nt < 8; nt++)
                            MMA_F16(o[nt], pah[kc], vh[nt]);
                    }
                }
            }
            __syncthreads();
        }

        l0 += __shfl_xor_sync(0xffffffffu, l0, 1);
        l0 += __shfl_xor_sync(0xffffffffu, l0, 2);
        l1 += __shfl_xor_sync(0xffffffffu, l1, 1);
        l1 += __shfl_xor_sync(0xffffffffu, l1, 2);
        const float i0 = 1.f / l0, i1 = 1.f / l1;

        if (phase == 0) {
            #pragma unroll
            for (int nt = 0; nt < 8; nt++) {
                const int c = nt * 8 + ccol;
                sO[rloc * 68 + c]           = o[nt][0] * i0;
                sO[rloc * 68 + c + 1]       = o[nt][1] * i0;
                sO[(rloc + 8) * 68 + c]     = o[nt][2] * i1;
                sO[(rloc + 8) * 68 + c + 1] = o[nt][3] * i1;
            }
        } else {
            const int r0 = q0 + wid * 16 + crow;
            __half* yh0 = Yh + ((size_t)b * Tt + r0) * Cc + h * Dd;
            __half* yh1 = yh0 + 8 * Cc;
            #pragma unroll
            for (int nt = 0; nt < 8; nt++) {
                const int c = nt * 8 + ccol;
                float vx0 = sO[rloc * 68 + c]           + o[nt][0] * i0;
                float vy0 = sO[rloc * 68 + c + 1]       + o[nt][1] * i0;
                float vx1 = sO[(rloc + 8) * 68 + c]     + o[nt][2] * i1;
                float vy1 = sO[(rloc + 8) * 68 + c + 1] + o[nt][3] * i1;
                __half2 h0 = __float22half2_rn(make_float2(vx0, vy0));
                __half2 h1 = __float22half2_rn(make_float2(vx1, vy1));
                *(uint32_t*)&yh0[c] = *(uint32_t*)&h0;
                *(uint32_t*)&yh1[c] = *(uint32_t*)&h1;
            }
        }
    }
}

// ---------------------------------------------------------------------------

extern "C" void kernel_launch(void* const* d_in, const int* in_sizes, int n_in,
                              void* d_out, int out_size)
{
    const float* x     = (const float*)d_in[0];
    const float* cross = (const float*)d_in[1];
    const float* Wk  = (const float*)d_in[2];   const float* bk  = (const float*)d_in[3];
    const float* Wq  = (const float*)d_in[4];   const float* bq  = (const float*)d_in[5];
    const float* Wv  = (const float*)d_in[6];   const float* bv  = (const float*)d_in[7];
    const float* Wck = (const float*)d_in[8];   const float* bck = (const float*)d_in[9];
    const float* Wcq = (const float*)d_in[10];  const float* bcq = (const float*)d_in[11];
    const float* Wcv = (const float*)d_in[12];  const float* bcv = (const float*)d_in[13];
    const float* Wp  = (const float*)d_in[14];  const float* bp  = (const float*)d_in[15];
    float* out = (float*)d_out;

    __half *xh, *ch, *cl, *yh;
    cudaGetSymbolAddress((void**)&xh, g_xh);
    cudaGetSymbolAddress((void**)&ch, g_ch); cudaGetSymbolAddress((void**)&cl, g_cl);
    cudaGetSymbolAddress((void**)&yh, g_yh);

    __half *qkvh, *kvch;
    cudaGetSymbolAddress((void**)&qkvh, g_qkvh);
    cudaGetSymbolAddress((void**)&kvch, g_kvch);

    __half *w4h, *w2h, *wph;
    cudaGetSymbolAddress((void**)&w4h, g_W4_h);
    cudaGetSymbolAddress((void**)&w2h, g_W2_h);
    cudaGetSymbolAddress((void**)&wph, g_Wp_h);
    float *b4, *b2;
    cudaGetSymbolAddress((void**)&b4, g_b4); cudaGetSymbolAddress((void**)&b2, g_b2);

    // prep
    transpose_all_kernel<<<dim3(32, 32, 7), dim3(32, 8)>>>(Wq, Wk, Wv, Wcq, Wck, Wcv, Wp);
    bias_concat_kernel<<<24, 256>>>(bq, bk, bv, bcq, bck, bcv);
    const int nx = Bb * Tt * Cc, nc = Bb * TCc * CCc;
    cvt_single_kernel<<<(nx + 255) / 256, 256>>>(x, xh, nx);
    cvt_pair_kernel<<<(nc + 255) / 256, 256>>>(cross, ch, cl, nc);

    const int SM1 = 3 * 2 * TILEB;   // 1-term GEMM smem (61440)
    const int SM2 = 3 * 3 * TILEB;   // 2-term GEMM smem (92160)
    cudaFuncSetAttribute(hmma_gemm_kernel<false>,
                         cudaFuncAttributeMaxDynamicSharedMemorySize, SM1);
    cudaFuncSetAttribute(hmma_gemm_kernel<true>,
                         cudaFuncAttributeMaxDynamicSharedMemorySize, SM2);
    const dim3 gblk(256);

    // QKV projection: single x @ single W4 -> single qkv
    hmma_gemm_kernel<false><<<dim3(32, 32), gblk, SM1>>>(
        xh, nullptr, w4h, b4, nullptr, qkvh, Bb*Tt, 4*Cc, Cc);
    // cross projection: (ch+cl) @ single W2 -> single kvc
    hmma_gemm_kernel<true><<<dim3(16, 8), gblk, SM2>>>(
        ch, cl, w2h, b2, nullptr, kvch, Bb*TCc, 2*Cc, CCc);

    cudaFuncSetAttribute(attn_fused_kernel, cudaFuncAttributeMaxDynamicSharedMemorySize, ATT_SMEM);
    attn_fused_kernel<<<dim3(Tt / 128, Hh, Bb), gblk, ATT_SMEM>>>(
        qkvh, kvch, yh);

    // output projection: single y @ single Wp -> fp32 out
    hmma_gemm_kernel<false><<<dim3(8, 32), gblk, SM1>>>(
        yh, nullptr, wph, bp, out, nullptr, Bb*Tt, Cc, Cc);
}

// round 14
// speedup vs baseline: 1.0584x; 1.0566x over previous
#include <cuda_runtime.h>
#include <cuda_fp16.h>
#include <cstdint>
#include <math.h>

#define Bb 2
#define Tt 2048
#define TCc 512
#define Cc 1024
#define CCc 512
#define Hh 16
#define Dd 64

#define NX (Bb*Tt*Cc)      // 4194304
#define NC (Bb*TCc*CCc)    // 524288

// ---------------------------------------------------------------------------
// Scratch (__device__ globals; no allocation allowed)
// ---------------------------------------------------------------------------
__device__ __half g_xh[NX];
__device__ __half g_ch[NC];
__device__ __half g_yh[Bb*Tt*Cc];

// fused projection outputs: [B*T, 4096] = [q | k | v | qc], single fp16
__device__ __half g_qkvh[Bb*Tt*4*Cc];
// fused cross outputs: [B*TC, 2048] = [kc | vc], single fp16
__device__ __half g_kvch[Bb*TCc*2*Cc];

// fused transposed weights (single fp16)
__device__ __half g_W4_h[4*Cc*Cc];
__device__ __half g_W2_h[2*Cc*CCc];
__device__ __half g_Wp_h[Cc*Cc];
__device__ float g_b4[4*Cc], g_b2[2*Cc];

// ---------------------------------------------------------------------------
// helpers
// ---------------------------------------------------------------------------
__device__ __forceinline__ uint32_t smem_u32(const void* p) {
    uint32_t a;
    asm("{ .reg .u64 t; cvta.to.shared.u64 t, %1; cvt.u32.u64 %0, t; }"
        : "=r"(a) : "l"(p));
    return a;
}
__device__ __forceinline__ float ex2(float x) {
    float y; asm("ex2.approx.ftz.f32 %0, %1;" : "=f"(y) : "f"(x)); return y;
}

#define CP_ASYNC16(dst, src) \
    asm volatile("cp.async.cg.shared.global [%0], [%1], 16;" :: "r"(dst), "l"(src))
#define CP_COMMIT() asm volatile("cp.async.commit_group;" ::: "memory")
#define CP_WAIT0()  asm volatile("cp.async.wait_group 0;" ::: "memory")
#define CP_WAIT1()  asm volatile("cp.async.wait_group 1;" ::: "memory")

#define LDSM_X4(r0, r1, r2, r3, a) \
    asm volatile("ldmatrix.sync.aligned.m8n8.x4.shared.b16 {%0,%1,%2,%3}, [%4];" \
                 : "=r"(r0), "=r"(r1), "=r"(r2), "=r"(r3) : "r"(a))
#define LDSM_X4T(r0, r1, r2, r3, a) \
    asm volatile("ldmatrix.sync.aligned.m8n8.x4.trans.shared.b16 {%0,%1,%2,%3}, [%4];" \
                 : "=r"(r0), "=r"(r1), "=r"(r2), "=r"(r3) : "r"(a))

#define MMA_F16(d, a, b) \
    asm volatile("mma.sync.aligned.m16n8k16.row.col.f32.f16.f16.f32 " \
                 "{%0,%1,%2,%3}, {%4,%5,%6,%7}, {%8,%9}, {%0,%1,%2,%3};" \
                 : "+f"((d)[0]), "+f"((d)[1]), "+f"((d)[2]), "+f"((d)[3]) \
                 : "r"((a)[0]), "r"((a)[1]), "r"((a)[2]), "r"((a)[3]), \
                   "r"((b)[0]), "r"((b)[1]))

// ---------------------------------------------------------------------------
// prep kernels
// ---------------------------------------------------------------------------
// fused: cvt x (single), cvt cross (single), bias concat — one 1D launch
__global__ void prep_misc_kernel(
    const float* __restrict__ x, const float* __restrict__ cross,
    const float* __restrict__ bq, const float* __restrict__ bk,
    const float* __restrict__ bv, const float* __restrict__ bcq,
    const float* __restrict__ bck, const float* __restrict__ bcv)
{
    int i = blockIdx.x * blockDim.x + threadIdx.x;
    if (i < NX) {
        g_xh[i] = __float2half(x[i]);
    } else if (i < NX + NC) {
        g_ch[i - NX] = __float2half(cross[i - NX]);
    } else {
        int j = i - NX - NC;
        if (j < 4096) {
            const float* s[4] = {bq, bk, bv, bcq};
            g_b4[j] = s[j >> 10][j & 1023];
        } else if (j < 6144) {
            int k = j - 4096;
            g_b2[k] = (k < 1024) ? bck[k] : bcv[k - 1024];
        }
    }
}

__global__ void transpose_all_kernel(
    const float* __restrict__ Wq,  const float* __restrict__ Wk,
    const float* __restrict__ Wv,  const float* __restrict__ Wcq,
    const float* __restrict__ Wck, const float* __restrict__ Wcv,
    const float* __restrict__ Wp)
{
    const int z = blockIdx.z;
    const float* W;
    __half* Th;
    int K;
    switch (z) {
        case 0: W = Wq;  Th = g_W4_h;               K = 1024; break;
        case 1: W = Wk;  Th = g_W4_h + 1024 * 1024; K = 1024; break;
        case 2: W = Wv;  Th = g_W4_h + 2048 * 1024; K = 1024; break;
        case 3: W = Wcq; Th = g_W4_h + 3072 * 1024; K = 1024; break;
        case 4: W = Wck; Th = g_W2_h;               K = 512;  break;
        case 5: W = Wcv; Th = g_W2_h + 1024 * 512;  K = 512;  break;
        default: W = Wp; Th = g_Wp_h;               K = 1024; break;
    }
    if (K == 512 && blockIdx.y >= 16) return;

    __shared__ float t[32][33];
    const int n0 = blockIdx.x * 32, k0 = blockIdx.y * 32;
    const int tx = threadIdx.x, ty = threadIdx.y;
    #pragma unroll
    for (int i = 0; i < 4; i++)
        t[ty + 8 * i][tx] = W[(size_t)(k0 + ty + 8 * i) * 1024 + n0 + tx];
    __syncthreads();
    #pragma unroll
    for (int i = 0; i < 4; i++) {
        float v = t[tx][ty + 8 * i];
        Th[(size_t)(n0 + ty + 8 * i) * K + k0 + tx] = __float2half(v);
    }
}

// ---------------------------------------------------------------------------
// single-term HMMA GEMM body (shared by dual + out kernels)
// out = Ah @ Bh^T + bias; 3-stage cp.async pipeline, 2 tiles/stage.
// ---------------------------------------------------------------------------
#define BKg 32
#define LDAg 40
#define TILEB (128 * LDAg * 2)
#define STG1 (2 * TILEB)
#define SM1 (3 * STG1)          // 61440

__device__ __forceinline__ void gemm_body(
    const __half* Ah, const __half* Bh, const float* bias,
    float* outf, __half* outh,
    int N, int K, int bm, int bn, char* smem)
{
    const uint32_t sb = smem_u32(smem);
    const int tid = threadIdx.x;
    const int wid = tid >> 5, lane = tid & 31;
    const int wr = wid & 3;
    const int wc = wid >> 2;

    const char* gA = (const char*)(Ah + (size_t)bm * K);
    const char* gB = (const char*)(Bh + (size_t)bn * K);

    const int row0 = tid >> 2, c16a = tid & 3;
    const int row1 = (tid + 256) >> 2;

    auto load_tile = [&](const char* g, uint32_t d, int kb) {
        g += (size_t)kb * (BKg * 2);
        CP_ASYNC16(d + row0 * (LDAg * 2) + c16a * 16,
                   g + (size_t)row0 * (K * 2) + c16a * 16);
        CP_ASYNC16(d + row1 * (LDAg * 2) + c16a * 16,
                   g + (size_t)row1 * (K * 2) + c16a * 16);
    };
    auto load_chunk = [&](int kb, int st) {
        const uint32_t sdst = sb + st * STG1;
        load_tile(gA, sdst, kb);
        load_tile(gB, sdst + TILEB, kb);
    };

    float acc[2][8][4] = {};

    const int nchunks = K / BKg;
    load_chunk(0, 0); CP_COMMIT();
    load_chunk(1, 1); CP_COMMIT();

    for (int kb = 0; kb < nchunks; kb++) {
        const int st = kb % 3;
        if (kb + 1 < nchunks) { CP_WAIT1(); } else { CP_WAIT0(); }
        __syncthreads();
        if (kb + 2 < nchunks) { load_chunk(kb + 2, (kb + 2) % 3); CP_COMMIT(); }

        const uint32_t ah = sb + st * STG1;
        const uint32_t bh = ah + TILEB;

        #pragma unroll
        for (int ks = 0; ks < 2; ks++) {
            const int k0 = ks * 16;
            uint32_t Ahf[2][4], Bhf[8][2];

            #pragma unroll
            for (int mt = 0; mt < 2; mt++) {
                const int arow = wr * 32 + mt * 16 + (lane & 15);
                const int acol = k0 + (lane >> 4) * 8;
                const uint32_t ao = (uint32_t)(arow * LDAg + acol) * 2;
                LDSM_X4(Ahf[mt][0], Ahf[mt][1], Ahf[mt][2], Ahf[mt][3], ah + ao);
            }
            #pragma unroll
            for (int np = 0; np < 4; np++) {
                const int brow = wc * 64 + np * 16 + ((lane >> 4) & 1) * 8 + (lane & 7);
                const int bcol = k0 + ((lane >> 3) & 1) * 8;
                const uint32_t bo = (uint32_t)(brow * LDAg + bcol) * 2;
                LDSM_X4(Bhf[2*np][0], Bhf[2*np][1], Bhf[2*np+1][0], Bhf[2*np+1][1], bh + bo);
            }

            #pragma unroll
            for (int mt = 0; mt < 2; mt++)
                #pragma unroll
                for (int nt = 0; nt < 8; nt++)
                    MMA_F16(acc[mt][nt], Ahf[mt], Bhf[nt]);
        }
    }

    const int crow = lane >> 2, ccol = (lane & 3) * 2;
    #pragma unroll
    for (int mt = 0; mt < 2; mt++) {
        #pragma unroll
        for (int hf2 = 0; hf2 < 2; hf2++) {
            const int r = bm + wr * 32 + mt * 16 + crow + hf2 * 8;
            #pragma unroll
            for (int nt = 0; nt < 8; nt++) {
                const int c = bn + wc * 64 + nt * 8 + ccol;
                float2 b2 = *(const float2*)&bias[c];
                float vx = acc[mt][nt][hf2 * 2 + 0] + b2.x;
                float vy = acc[mt][nt][hf2 * 2 + 1] + b2.y;
                if (outf) {
                    float2 v; v.x = vx; v.y = vy;
                    *(float2*)&outf[(size_t)r * N + c] = v;
                } else {
                    __half2 hh = __float22half2_rn(make_float2(vx, vy));
                    *(uint32_t*)&outh[(size_t)r * N + c] = *(uint32_t*)&hh;
                }
            }
        }
    }
}

// unified projection launch: tiles [0, T1) = QKV gemm, [T1, T1+T2) = cross gemm
#define T1_TILES 1024   // 32 bn x 32 bm  (M=4096, N=4096, K=1024)
#define T2_TILES 128    // 16 bn x 8 bm   (M=1024, N=2048, K=512)

__global__ __launch_bounds__(256, 2) void proj_dual_kernel()
{
    extern __shared__ char smem[];
    int t = blockIdx.x;
    if (t < T1_TILES) {
        const int bn = (t & 31) * 128, bm = (t >> 5) * 128;
        gemm_body(g_xh, g_W4_h, g_b4, nullptr, g_qkvh, 4*Cc, Cc, bm, bn, smem);
    } else {
        t -= T1_TILES;
        // cross: N = 2048 -> 16 bn tiles, M = 1024 -> 8 bm tiles
        const int bn = (t & 15) * 128, bm = (t >> 4) * 128;
        gemm_body(g_ch, g_W2_h, g_b2, nullptr, g_kvch, 2*Cc, CCc, bm, bn, smem);
    }
}

// output projection (fp32 out, bias bp)
__global__ __launch_bounds__(256, 2) void out_proj_kernel(
    const float* __restrict__ bp, float* __restrict__ out)
{
    extern __shared__ char smem[];
    const int bn = blockIdx.x * 128, bm = blockIdx.y * 128;
    gemm_body(g_yh, g_Wp_h, bp, out, nullptr, Cc, Cc, bm, bn, smem);
}

// ---------------------------------------------------------------------------
// Fused HMMA flash attention (all single fp16 operands), 2 CTAs/SM.
// ---------------------------------------------------------------------------
#define APB 144
#define QTILE (128 * APB)               // 18432
#define KVTILE (64 * APB)               // 9216
#define KVSTAGE (2 * KVTILE)            // 18432
#define SO_OFF (QTILE + 2 * KVSTAGE)    // 55296
#define ATT_SMEM (SO_OFF + 128 * 68 * 4)   // 90112

__global__ __launch_bounds__(256, 2) void attn_fused_kernel(
    const __half* __restrict__ qkvh,
    const __half* __restrict__ kvch, __half* __restrict__ Yh)
{
    extern __shared__ char smem[];
    const uint32_t sb = smem_u32(smem);
    float* sO = (float*)(smem + SO_OFF);
    const int tid = threadIdx.x, wid = tid >> 5, lane = tid & 31;
    const int qt = gridDim.x - 1 - blockIdx.x;   // heavy first
    const int h = blockIdx.y, b = blockIdx.z;
    const int q0 = qt * 128;

    const uint32_t sQh = sb;
    const uint32_t sKV = sb + QTILE;

    const int crow = lane >> 2, ccol = (lane & 3) * 2;
    const int rloc = wid * 16 + crow;
    const int wrow = q0 + wid * 16;
    const float cs = 0.125f * 1.44269504089f;

    for (int phase = 0; phase < 2; phase++) {
        const bool causal = (phase == 0);
        const int ldq  = 4 * Cc;
        const int ldkv = causal ? 4 * Cc : 2 * Cc;
        const int ntt  = causal ? (2 * qt + 2) : (TCc / 64);

        const __half* Qhp = causal ? qkvh        : qkvh + 3072;
        const __half* Khp = causal ? qkvh + 1024 : kvch;
        const __half* Vhp = causal ? qkvh + 2048 : kvch + 1024;

        const size_t qoff = ((size_t)b * Tt + q0) * ldq + h * Dd;
        const size_t koff = ((size_t)b * (causal ? Tt : TCc)) * ldkv + h * Dd;

        // ---- load Q ----
        {
            const char* gq = (const char*)(Qhp + qoff);
            #pragma unroll
            for (int it = 0; it < 4; it++) {
                int idx = it * 256 + tid;
                int r = idx >> 3, c = idx & 7;
                CP_ASYNC16(sQh + r * APB + c * 16,
                           gq + (size_t)r * (ldq * 2) + c * 16);
            }
        }
        CP_COMMIT();

        const char* gk[2] = { (const char*)(Khp + koff), (const char*)(Vhp + koff) };
        auto load_kv = [&](int kt, int st) {
            uint32_t dst = sKV + st * KVSTAGE;
            #pragma unroll
            for (int m = 0; m < 2; m++) {
                #pragma unroll
                for (int it = 0; it < 2; it++) {
                    int idx = it * 256 + tid;
                    int r = idx >> 3, c = idx & 7;
                    CP_ASYNC16(dst + m * KVTILE + r * APB + c * 16,
                               gk[m] + ((size_t)(kt * 64 + r)) * (ldkv * 2) + c * 16);
                }
            }
        };

        load_kv(0, 0);
        CP_COMMIT();
        CP_WAIT1();
        __syncthreads();

        uint32_t Qhf[4][4];
        {
            const int r = wid * 16 + (lane & 7) + 8 * ((lane >> 3) & 1);
            const int cb = 8 * (lane >> 4);
            #pragma unroll
            for (int kc = 0; kc < 4; kc++) {
                const uint32_t off = (uint32_t)r * APB + (kc * 16 + cb) * 2;
                LDSM_X4(Qhf[kc][0], Qhf[kc][1], Qhf[kc][2], Qhf[kc][3], sQh + off);
            }
        }

        float o[8][4] = {};
        float m0 = -1e30f, m1 = -1e30f, l0 = 0.f, l1 = 0.f;

        for (int kt = 0; kt < ntt; kt++) {
            const int st = kt & 1;
            if (kt + 1 < ntt) { load_kv(kt + 1, st ^ 1); CP_COMMIT(); CP_WAIT1(); }
            else              { CP_WAIT0(); }
            __syncthreads();

            const int k0 = kt * 64;
            const bool active = !causal || (k0 <= wrow + 15);
            if (active) {
                const uint32_t sKhT = sKV + st * KVSTAGE;
                const uint32_t sVhT = sKhT + KVTILE;

                // ---- S = Qh Kh^T ----
                float s[8][4] = {};
                {
                    const int krow = (lane & 7) + 8 * (lane >> 4);
                    const int kcolb = 8 * ((lane >> 3) & 1);
                    #pragma unroll
                    for (int kc = 0; kc < 4; kc++) {
                        uint32_t bh[8][2];
                        #pragma unroll
                        for (int np = 0; np < 4; np++) {
                            const uint32_t off =
                                (uint32_t)(np * 16 + krow) * APB + (kc * 16 + kcolb) * 2;
                            LDSM_X4(bh[2*np][0], bh[2*np][1], bh[2*np+1][0], bh[2*np+1][1],
                                    sKhT + off);
                        }
                        #pragma unroll
                        for (int nt = 0; nt < 8; nt++)
                            MMA_F16(s[nt], Qhf[kc], bh[nt]);
                    }
                }

                const bool dm = causal && (k0 + 63 > wrow);
                float zx0 = -1e30f, zx1 = -1e30f;
                #pragma unroll
                for (int nt = 0; nt < 8; nt++) {
                    #pragma unroll
                    for (int r = 0; r < 4; r++) {
                        float z = s[nt][r] * cs;
                        if (dm) {
                            const int col = k0 + nt * 8 + ccol + (r & 1);
                            const int row = wrow + crow + 8 * (r >> 1);
                            if (col > row) z = -1e30f;
                        }
                        s[nt][r] = z;
                    }
                    zx0 = fmaxf(zx0, fmaxf(s[nt][0], s[nt][1]));
                    zx1 = fmaxf(zx1, fmaxf(s[nt][2], s[nt][3]));
                }
                zx0 = fmaxf(zx0, __shfl_xor_sync(0xffffffffu, zx0, 1));
                zx0 = fmaxf(zx0, __shfl_xor_sync(0xffffffffu, zx0, 2));
                zx1 = fmaxf(zx1, __shfl_xor_sync(0xffffffffu, zx1, 1));
                zx1 = fmaxf(zx1, __shfl_xor_sync(0xffffffffu, zx1, 2));
                const float mn0 = fmaxf(m0, zx0), mn1 = fmaxf(m1, zx1);
                const float a0 = ex2(m0 - mn0), a1 = ex2(m1 - mn1);
                m0 = mn0; m1 = mn1;

                float ps0 = 0.f, ps1 = 0.f;
                uint32_t pah[4][4];
                #pragma unroll
                for (int nt = 0; nt < 8; nt++) {
                    const float p0 = ex2(s[nt][0] - mn0), p1 = ex2(s[nt][1] - mn0);
                    const float p2 = ex2(s[nt][2] - mn1), p3 = ex2(s[nt][3] - mn1);
                    ps0 += p0 + p1; ps1 += p2 + p3;
                    __half2 h01 = __float22half2_rn(make_float2(p0, p1));
                    __half2 h23 = __float22half2_rn(make_float2(p2, p3));
                    pah[nt >> 1][(nt & 1) * 2 + 0] = *(uint32_t*)&h01;
                    pah[nt >> 1][(nt & 1) * 2 + 1] = *(uint32_t*)&h23;
                }
                l0 = l0 * a0 + ps0;
                l1 = l1 * a1 + ps1;
                #pragma unroll
                for (int nt = 0; nt < 8; nt++) {
                    o[nt][0] *= a0; o[nt][1] *= a0;
                    o[nt][2] *= a1; o[nt][3] *= a1;
                }

                // ---- O += Ph Vh ----
                {
                    const int vrl = (lane & 7) + 8 * ((lane >> 3) & 1);
                    const int vcb = 8 * (lane >> 4);
                    #pragma unroll
                    for (int kc = 0; kc < 4; kc++) {
                        uint32_t vh[8][2];
                        #pragma unroll
                        for (int dp = 0; dp < 4; dp++) {
                            const uint32_t off =
                                (uint32_t)(kc * 16 + vrl) * APB + (dp * 16 + vcb) * 2;
                            LDSM_X4T(vh[2*dp][0], vh[2*dp][1], vh[2*dp+1][0], vh[2*dp+1][1],
                                     sVhT + off);
                        }
                        #pragma unroll
                        for (int nt = 0; nt < 8; nt++)
                            MMA_F16(o[nt], pah[kc], vh[nt]);
                    }
                }
            }
            __syncthreads();
        }

        l0 += __shfl_xor_sync(0xffffffffu, l0, 1);
        l0 += __shfl_xor_sync(0xffffffffu, l0, 2);
        l1 += __shfl_xor_sync(0xffffffffu, l1, 1);
        l1 += __shfl_xor_sync(0xffffffffu, l1, 2);
        const float i0 = 1.f / l0, i1 = 1.f / l1;

        if (phase == 0) {
            #pragma unroll
            for (int nt = 0; nt < 8; nt++) {
                const int c = nt * 8 + ccol;
                sO[rloc * 68 + c]           = o[nt][0] * i0;
                sO[rloc * 68 + c + 1]       = o[nt][1] * i0;
                sO[(rloc + 8) * 68 + c]     = o[nt][2] * i1;
                sO[(rloc + 8) * 68 + c + 1] = o[nt][3] * i1;
            }
        } else {
            const int r0 = q0 + wid * 16 + crow;
            __half* yh0 = Yh + ((size_t)b * Tt + r0) * Cc + h * Dd;
            __half* yh1 = yh0 + 8 * Cc;
            #pragma unroll
            for (int nt = 0; nt < 8; nt++) {
                const int c = nt * 8 + ccol;
                float vx0 = sO[rloc * 68 + c]           + o[nt][0] * i0;
                float vy0 = sO[rloc * 68 + c + 1]       + o[nt][1] * i0;
                float vx1 = sO[(rloc + 8) * 68 + c]     + o[nt][2] * i1;
                float vy1 = sO[(rloc + 8) * 68 + c + 1] + o[nt][3] * i1;
                __half2 h0 = __float22half2_rn(make_float2(vx0, vy0));
                __half2 h1 = __float22half2_rn(make_float2(vx1, vy1));
                *(uint32_t*)&yh0[c] = *(uint32_t*)&h0;
                *(uint32_t*)&yh1[c] = *(uint32_t*)&h1;
            }
        }
    }
}

// ---------------------------------------------------------------------------

extern "C" void kernel_launch(void* const* d_in, const int* in_sizes, int n_in,
                              void* d_out, int out_size)
{
    const float* x     = (const float*)d_in[0];
    const float* cross = (const float*)d_in[1];
    const float* Wk  = (const float*)d_in[2];   const float* bk  = (const float*)d_in[3];
    const float* Wq  = (const float*)d_in[4];   const float* bq  = (const float*)d_in[5];
    const float* Wv  = (const float*)d_in[6];   const float* bv  = (const float*)d_in[7];
    const float* Wck = (const float*)d_in[8];   const float* bck = (const float*)d_in[9];
    const float* Wcq = (const float*)d_in[10];  const float* bcq = (const float*)d_in[11];
    const float* Wcv = (const float*)d_in[12];  const float* bcv = (const float*)d_in[13];
    const float* Wp  = (const float*)d_in[14];  const float* bp  = (const float*)d_in[15];
    float* out = (float*)d_out;

    __half *qkvh, *kvch, *yh;
    cudaGetSymbolAddress((void**)&qkvh, g_qkvh);
    cudaGetSymbolAddress((void**)&kvch, g_kvch);
    cudaGetSymbolAddress((void**)&yh, g_yh);

    // prep: weights transpose + (cvt x, cvt cross, bias concat)
    transpose_all_kernel<<<dim3(32, 32, 7), dim3(32, 8)>>>(Wq, Wk, Wv, Wcq, Wck, Wcv, Wp);
    const int ntot = NX + NC + 6144;
    prep_misc_kernel<<<(ntot + 255) / 256, 256>>>(x, cross, bq, bk, bv, bcq, bck, bcv);

    cudaFuncSetAttribute(proj_dual_kernel, cudaFuncAttributeMaxDynamicSharedMemorySize, SM1);
    cudaFuncSetAttribute(out_proj_kernel,  cudaFuncAttributeMaxDynamicSharedMemorySize, SM1);
    cudaFuncSetAttribute(attn_fused_kernel, cudaFuncAttributeMaxDynamicSharedMemorySize, ATT_SMEM);
    const dim3 gblk(256);

    // unified projections: QKV tiles first, cross tiles fill the tail wave
    proj_dual_kernel<<<T1_TILES + T2_TILES, gblk, SM1>>>();

    // fused attention (self causal + cross), 2 CTAs/SM
    attn_fused_kernel<<<dim3(Tt / 128, Hh, Bb), gblk, ATT_SMEM>>>(qkvh, kvch, yh);

    // output projection
    out_proj_kernel<<<dim3(Cc / 128, (Bb * Tt) / 128), gblk, SM1>>>(bp, out);
}

// round 15
// speedup vs baseline: 1.1896x; 1.1239x over previous
#include <cuda_runtime.h>
#include <cuda_fp16.h>
#include <cstdint>
#include <math.h>

#define Bb 2
#define Tt 2048
#define TCc 512
#define Cc 1024
#define CCc 512
#define Hh 16
#define Dd 64

#define NX (Bb*Tt*Cc)      // 4194304
#define NC (Bb*TCc*CCc)    // 524288

// ---------------------------------------------------------------------------
// Scratch (__device__ globals; no allocation allowed)
// ---------------------------------------------------------------------------
__device__ __half g_xh[NX];
__device__ __half g_ch[NC];
__device__ __half g_yh[Bb*Tt*Cc];

// fused projection outputs: [B*T, 4096] = [q | k | v | qc], single fp16
// q and qc columns are PRE-SCALED by cs = 0.125 * log2(e).
__device__ __half g_qkvh[Bb*Tt*4*Cc];
// fused cross outputs: [B*TC, 2048] = [kc | vc], single fp16
__device__ __half g_kvch[Bb*TCc*2*Cc];

// fused transposed weights (single fp16)
__device__ __half g_W4_h[4*Cc*Cc];
__device__ __half g_W2_h[2*Cc*CCc];
__device__ __half g_Wp_h[Cc*Cc];
__device__ float g_b4[4*Cc], g_b2[2*Cc];

// persistent attention work counter
__device__ int g_actr;

#define CSF 0.18033688011f   // 0.125 * log2(e)

// ---------------------------------------------------------------------------
// helpers
// ---------------------------------------------------------------------------
__device__ __forceinline__ uint32_t smem_u32(const void* p) {
    uint32_t a;
    asm("{ .reg .u64 t; cvta.to.shared.u64 t, %1; cvt.u32.u64 %0, t; }"
        : "=r"(a) : "l"(p));
    return a;
}
__device__ __forceinline__ float ex2(float x) {
    float y; asm("ex2.approx.ftz.f32 %0, %1;" : "=f"(y) : "f"(x)); return y;
}

#define CP_ASYNC16(dst, src) \
    asm volatile("cp.async.cg.shared.global [%0], [%1], 16;" :: "r"(dst), "l"(src))
#define CP_COMMIT() asm volatile("cp.async.commit_group;" ::: "memory")
#define CP_WAIT0()  asm volatile("cp.async.wait_group 0;" ::: "memory")
#define CP_WAIT1()  asm volatile("cp.async.wait_group 1;" ::: "memory")

#define LDSM_X4(r0, r1, r2, r3, a) \
    asm volatile("ldmatrix.sync.aligned.m8n8.x4.shared.b16 {%0,%1,%2,%3}, [%4];" \
                 : "=r"(r0), "=r"(r1), "=r"(r2), "=r"(r3) : "r"(a))
#define LDSM_X4T(r0, r1, r2, r3, a) \
    asm volatile("ldmatrix.sync.aligned.m8n8.x4.trans.shared.b16 {%0,%1,%2,%3}, [%4];" \
                 : "=r"(r0), "=r"(r1), "=r"(r2), "=r"(r3) : "r"(a))

#define MMA_F16(d, a, b) \
    asm volatile("mma.sync.aligned.m16n8k16.row.col.f32.f16.f16.f32 " \
                 "{%0,%1,%2,%3}, {%4,%5,%6,%7}, {%8,%9}, {%0,%1,%2,%3};" \
                 : "+f"((d)[0]), "+f"((d)[1]), "+f"((d)[2]), "+f"((d)[3]) \
                 : "r"((a)[0]), "r"((a)[1]), "r"((a)[2]), "r"((a)[3]), \
                   "r"((b)[0]), "r"((b)[1]))

// ---------------------------------------------------------------------------
// prep kernels
// ---------------------------------------------------------------------------
__global__ void prep_misc_kernel(
    const float* __restrict__ x, const float* __restrict__ cross,
    const float* __restrict__ bq, const float* __restrict__ bk,
    const float* __restrict__ bv, const float* __restrict__ bcq,
    const float* __restrict__ bck, const float* __restrict__ bcv)
{
    int i = blockIdx.x * blockDim.x + threadIdx.x;
    if (i == 0) g_actr = 0;   // reset persistent attention counter
    if (i < NX) {
        g_xh[i] = __float2half(x[i]);
    } else if (i < NX + NC) {
        g_ch[i - NX] = __float2half(cross[i - NX]);
    } else {
        int j = i - NX - NC;
        if (j < 4096) {
            const float* s[4] = {bq, bk, bv, bcq};
            g_b4[j] = s[j >> 10][j & 1023];
        } else if (j < 6144) {
            int k = j - 4096;
            g_b2[k] = (k < 1024) ? bck[k] : bcv[k - 1024];
        }
    }
}

__global__ void transpose_all_kernel(
    const float* __restrict__ Wq,  const float* __restrict__ Wk,
    const float* __restrict__ Wv,  const float* __restrict__ Wcq,
    const float* __restrict__ Wck, const float* __restrict__ Wcv,
    const float* __restrict__ Wp)
{
    const int z = blockIdx.z;
    const float* W;
    __half* Th;
    int K;
    switch (z) {
        case 0: W = Wq;  Th = g_W4_h;               K = 1024; break;
        case 1: W = Wk;  Th = g_W4_h + 1024 * 1024; K = 1024; break;
        case 2: W = Wv;  Th = g_W4_h + 2048 * 1024; K = 1024; break;
        case 3: W = Wcq; Th = g_W4_h + 3072 * 1024; K = 1024; break;
        case 4: W = Wck; Th = g_W2_h;               K = 512;  break;
        case 5: W = Wcv; Th = g_W2_h + 1024 * 512;  K = 512;  break;
        default: W = Wp; Th = g_Wp_h;               K = 1024; break;
    }
    if (K == 512 && blockIdx.y >= 16) return;

    __shared__ float t[32][33];
    const int n0 = blockIdx.x * 32, k0 = blockIdx.y * 32;
    const int tx = threadIdx.x, ty = threadIdx.y;
    #pragma unroll
    for (int i = 0; i < 4; i++)
        t[ty + 8 * i][tx] = W[(size_t)(k0 + ty + 8 * i) * 1024 + n0 + tx];
    __syncthreads();
    #pragma unroll
    for (int i = 0; i < 4; i++) {
        float v = t[tx][ty + 8 * i];
        Th[(size_t)(n0 + ty + 8 * i) * K + k0 + tx] = __float2half(v);
    }
}

// ---------------------------------------------------------------------------
// single-term HMMA GEMM body
// out = Ah @ Bh^T + bias; 3-stage cp.async pipeline, 2 tiles/stage.
// qscale=1: scale output by CSF for columns in [0,1024) or [3072,4096)
//           (the q / qc slices of the fused qkv output).
// ---------------------------------------------------------------------------
#define BKg 32
#define LDAg 40
#define TILEB (128 * LDAg * 2)
#define STG1 (2 * TILEB)
#define SM1 (3 * STG1)          // 61440

__device__ __forceinline__ void gemm_body(
    const __half* Ah, const __half* Bh, const float* bias,
    float* outf, __half* outh,
    int N, int K, int bm, int bn, int qscale, char* smem)
{
    const uint32_t sb = smem_u32(smem);
    const int tid = threadIdx.x;
    const int wid = tid >> 5, lane = tid & 31;
    const int wr = wid & 3;
    const int wc = wid >> 2;

    const char* gA = (const char*)(Ah + (size_t)bm * K);
    const char* gB = (const char*)(Bh + (size_t)bn * K);

    const int row0 = tid >> 2, c16a = tid & 3;
    const int row1 = (tid + 256) >> 2;

    auto load_tile = [&](const char* g, uint32_t d, int kb) {
        g += (size_t)kb * (BKg * 2);
        CP_ASYNC16(d + row0 * (LDAg * 2) + c16a * 16,
                   g + (size_t)row0 * (K * 2) + c16a * 16);
        CP_ASYNC16(d + row1 * (LDAg * 2) + c16a * 16,
                   g + (size_t)row1 * (K * 2) + c16a * 16);
    };
    auto load_chunk = [&](int kb, int st) {
        const uint32_t sdst = sb + st * STG1;
        load_tile(gA, sdst, kb);
        load_tile(gB, sdst + TILEB, kb);
    };

    float acc[2][8][4] = {};

    const int nchunks = K / BKg;
    load_chunk(0, 0); CP_COMMIT();
    load_chunk(1, 1); CP_COMMIT();

    for (int kb = 0; kb < nchunks; kb++) {
        const int st = kb % 3;
        if (kb + 1 < nchunks) { CP_WAIT1(); } else { CP_WAIT0(); }
        __syncthreads();
        if (kb + 2 < nchunks) { load_chunk(kb + 2, (kb + 2) % 3); CP_COMMIT(); }

        const uint32_t ah = sb + st * STG1;
        const uint32_t bh = ah + TILEB;

        #pragma unroll
        for (int ks = 0; ks < 2; ks++) {
            const int k0 = ks * 16;
            uint32_t Ahf[2][4], Bhf[8][2];

            #pragma unroll
            for (int mt = 0; mt < 2; mt++) {
                const int arow = wr * 32 + mt * 16 + (lane & 15);
                const int acol = k0 + (lane >> 4) * 8;
                const uint32_t ao = (uint32_t)(arow * LDAg + acol) * 2;
                LDSM_X4(Ahf[mt][0], Ahf[mt][1], Ahf[mt][2], Ahf[mt][3], ah + ao);
            }
            #pragma unroll
            for (int np = 0; np < 4; np++) {
                const int brow = wc * 64 + np * 16 + ((lane >> 4) & 1) * 8 + (lane & 7);
                const int bcol = k0 + ((lane >> 3) & 1) * 8;
                const uint32_t bo = (uint32_t)(brow * LDAg + bcol) * 2;
                LDSM_X4(Bhf[2*np][0], Bhf[2*np][1], Bhf[2*np+1][0], Bhf[2*np+1][1], bh + bo);
            }

            #pragma unroll
            for (int mt = 0; mt < 2; mt++)
                #pragma unroll
                for (int nt = 0; nt < 8; nt++)
                    MMA_F16(acc[mt][nt], Ahf[mt], Bhf[nt]);
        }
    }

    const int crow = lane >> 2, ccol = (lane & 3) * 2;
    // q/qc columns of the fused qkv output live at bn in [0,1024) or [3072,4096);
    // a whole 128-col tile is uniformly scaled or not.
    const float osc = (qscale && (bn < 1024 || bn >= 3072)) ? CSF : 1.0f;
    #pragma unroll
    for (int mt = 0; mt < 2; mt++) {
        #pragma unroll
        for (int hf2 = 0; hf2 < 2; hf2++) {
            const int r = bm + wr * 32 + mt * 16 + crow + hf2 * 8;
            #pragma unroll
            for (int nt = 0; nt < 8; nt++) {
                const int c = bn + wc * 64 + nt * 8 + ccol;
                float2 b2 = *(const float2*)&bias[c];
                float vx = (acc[mt][nt][hf2 * 2 + 0] + b2.x) * osc;
                float vy = (acc[mt][nt][hf2 * 2 + 1] + b2.y) * osc;
                if (outf) {
                    float2 v; v.x = vx; v.y = vy;
                    *(float2*)&outf[(size_t)r * N + c] = v;
                } else {
                    __half2 hh = __float22half2_rn(make_float2(vx, vy));
                    *(uint32_t*)&outh[(size_t)r * N + c] = *(uint32_t*)&hh;
                }
            }
        }
    }
}

// unified projection launch: tiles [0, T1) = QKV gemm, [T1, T1+T2) = cross gemm
#define T1_TILES 1024   // 32 bn x 32 bm  (M=4096, N=4096, K=1024)
#define T2_TILES 128    // 16 bn x 8 bm   (M=1024, N=2048, K=512)

__global__ __launch_bounds__(256, 2) void proj_dual_kernel()
{
    extern __shared__ char smem[];
    int t = blockIdx.x;
    if (t < T1_TILES) {
        const int bn = (t & 31) * 128, bm = (t >> 5) * 128;
        gemm_body(g_xh, g_W4_h, g_b4, nullptr, g_qkvh, 4*Cc, Cc, bm, bn, 1, smem);
    } else {
        t -= T1_TILES;
        const int bn = (t & 15) * 128, bm = (t >> 4) * 128;
        gemm_body(g_ch, g_W2_h, g_b2, nullptr, g_kvch, 2*Cc, CCc, bm, bn, 0, smem);
    }
}

// output projection (fp32 out, bias bp)
__global__ __launch_bounds__(256, 2) void out_proj_kernel(
    const float* __restrict__ bp, float* __restrict__ out)
{
    extern __shared__ char smem[];
    const int bn = blockIdx.x * 128, bm = blockIdx.y * 128;
    gemm_body(g_yh, g_Wp_h, bp, out, nullptr, Cc, Cc, bm, bn, 0, smem);
}

// ---------------------------------------------------------------------------
// Persistent fused HMMA flash attention (single fp16 operands), 2 CTAs/SM.
// Work items (512): qt descending (heavy first) x (h, b).
// q/qc pre-scaled by CSF, so S fragments are already in log2 domain.
// ---------------------------------------------------------------------------
#define APB 144
#define QTILE (128 * APB)               // 18432
#define KVTILE (64 * APB)               // 9216
#define KVSTAGE (2 * KVTILE)            // 18432
#define SO_OFF (QTILE + 2 * KVSTAGE)    // 55296
#define ATT_SMEM (SO_OFF + 128 * 68 * 4)   // 90112
#define N_WORK (Tt / 128 * Hh * Bb)     // 512

__global__ __launch_bounds__(256, 2) void attn_fused_kernel(
    const __half* __restrict__ qkvh,
    const __half* __restrict__ kvch, __half* __restrict__ Yh)
{
    extern __shared__ char smem[];
    const uint32_t sb = smem_u32(smem);
    float* sO = (float*)(smem + SO_OFF);
    const int tid = threadIdx.x, wid = tid >> 5, lane = tid & 31;

    const uint32_t sQh = sb;
    const uint32_t sKV = sb + QTILE;

    const int crow = lane >> 2, ccol = (lane & 3) * 2;
    const int rloc = wid * 16 + crow;

    __shared__ int s_work;

    for (;;) {
        if (tid == 0) s_work = atomicAdd(&g_actr, 1);
        __syncthreads();
        const int w = s_work;
        if (w >= N_WORK) break;

        // heavy-first decode: qt descends as w grows within groups of 32
        const int qt = (Tt / 128 - 1) - (w >> 5);
        const int hb = w & 31;
        const int h = hb & 15, b = hb >> 4;
        const int q0 = qt * 128;
        const int wrow = q0 + wid * 16;

        for (int phase = 0; phase < 2; phase++) {
            const bool causal = (phase == 0);
            const int ldq  = 4 * Cc;
            const int ldkv = causal ? 4 * Cc : 2 * Cc;
            const int ntt  = causal ? (2 * qt + 2) : (TCc / 64);

            const __half* Qhp = causal ? qkvh        : qkvh + 3072;
            const __half* Khp = causal ? qkvh + 1024 : kvch;
            const __half* Vhp = causal ? qkvh + 2048 : kvch + 1024;

            const size_t qoff = ((size_t)b * Tt + q0) * ldq + h * Dd;
            const size_t koff = ((size_t)b * (causal ? Tt : TCc)) * ldkv + h * Dd;

            // ---- load Q ----
            {
                const char* gq = (const char*)(Qhp + qoff);
                #pragma unroll
                for (int it = 0; it < 4; it++) {
                    int idx = it * 256 + tid;
                    int r = idx >> 3, c = idx & 7;
                    CP_ASYNC16(sQh + r * APB + c * 16,
                               gq + (size_t)r * (ldq * 2) + c * 16);
                }
            }
            CP_COMMIT();

            const char* gk[2] = { (const char*)(Khp + koff), (const char*)(Vhp + koff) };
            auto load_kv = [&](int kt, int st) {
                uint32_t dst = sKV + st * KVSTAGE;
                #pragma unroll
                for (int m = 0; m < 2; m++) {
                    #pragma unroll
                    for (int it = 0; it < 2; it++) {
                        int idx = it * 256 + tid;
                        int r = idx >> 3, c = idx & 7;
                        CP_ASYNC16(dst + m * KVTILE + r * APB + c * 16,
                                   gk[m] + ((size_t)(kt * 64 + r)) * (ldkv * 2) + c * 16);
                    }
                }
            };

            load_kv(0, 0);
            CP_COMMIT();
            CP_WAIT1();
            __syncthreads();

            uint32_t Qhf[4][4];
            {
                const int r = wid * 16 + (lane & 7) + 8 * ((lane >> 3) & 1);
                const int cb = 8 * (lane >> 4);
                #pragma unroll
                for (int kc = 0; kc < 4; kc++) {
                    const uint32_t off = (uint32_t)r * APB + (kc * 16 + cb) * 2;
                    LDSM_X4(Qhf[kc][0], Qhf[kc][1], Qhf[kc][2], Qhf[kc][3], sQh + off);
                }
            }

            float o[8][4] = {};
            float m0 = -1e30f, m1 = -1e30f, l0 = 0.f, l1 = 0.f;

            for (int kt = 0; kt < ntt; kt++) {
                const int st = kt & 1;
                if (kt + 1 < ntt) { load_kv(kt + 1, st ^ 1); CP_COMMIT(); CP_WAIT1(); }
                else              { CP_WAIT0(); }
                __syncthreads();

                const int k0 = kt * 64;
                const bool active = !causal || (k0 <= wrow + 15);
                if (active) {
                    const uint32_t sKhT = sKV + st * KVSTAGE;
                    const uint32_t sVhT = sKhT + KVTILE;

                    // ---- S = Qh Kh^T (already log2-scaled via prescaled Q) ----
                    float s[8][4] = {};
                    {
                        const int krow = (lane & 7) + 8 * (lane >> 4);
                        const int kcolb = 8 * ((lane >> 3) & 1);
                        #pragma unroll
                        for (int kc = 0; kc < 4; kc++) {
                            uint32_t bh[8][2];
                            #pragma unroll
                            for (int np = 0; np < 4; np++) {
                                const uint32_t off =
                                    (uint32_t)(np * 16 + krow) * APB + (kc * 16 + kcolb) * 2;
                                LDSM_X4(bh[2*np][0], bh[2*np][1], bh[2*np+1][0], bh[2*np+1][1],
                                        sKhT + off);
                            }
                            #pragma unroll
                            for (int nt = 0; nt < 8; nt++)
                                MMA_F16(s[nt], Qhf[kc], bh[nt]);
                        }
                    }

                    const bool dm = causal && (k0 + 63 > wrow);
                    float zx0 = -1e30f, zx1 = -1e30f;
                    #pragma unroll
                    for (int nt = 0; nt < 8; nt++) {
                        if (dm) {
                            #pragma unroll
                            for (int r = 0; r < 4; r++) {
                                const int col = k0 + nt * 8 + ccol + (r & 1);
                                const int row = wrow + crow + 8 * (r >> 1);
                                if (col > row) s[nt][r] = -1e30f;
                            }
                        }
                        zx0 = fmaxf(zx0, fmaxf(s[nt][0], s[nt][1]));
                        zx1 = fmaxf(zx1, fmaxf(s[nt][2], s[nt][3]));
                    }
                    zx0 = fmaxf(zx0, __shfl_xor_sync(0xffffffffu, zx0, 1));
                    zx0 = fmaxf(zx0, __shfl_xor_sync(0xffffffffu, zx0, 2));
                    zx1 = fmaxf(zx1, __shfl_xor_sync(0xffffffffu, zx1, 1));
                    zx1 = fmaxf(zx1, __shfl_xor_sync(0xffffffffu, zx1, 2));
                    const float mn0 = fmaxf(m0, zx0), mn1 = fmaxf(m1, zx1);
                    const float a0 = ex2(m0 - mn0), a1 = ex2(m1 - mn1);
                    m0 = mn0; m1 = mn1;

                    float ps0 = 0.f, ps1 = 0.f;
                    uint32_t pah[4][4];
                    #pragma unroll
                    for (int nt = 0; nt < 8; nt++) {
                        const float p0 = ex2(s[nt][0] - mn0), p1 = ex2(s[nt][1] - mn0);
                        const float p2 = ex2(s[nt][2] - mn1), p3 = ex2(s[nt][3] - mn1);
                        ps0 += p0 + p1; ps1 += p2 + p3;
                        __half2 h01 = __float22half2_rn(make_float2(p0, p1));
                        __half2 h23 = __float22half2_rn(make_float2(p2, p3));
                        pah[nt >> 1][(nt & 1) * 2 + 0] = *(uint32_t*)&h01;
                        pah[nt >> 1][(nt & 1) * 2 + 1] = *(uint32_t*)&h23;
                    }
                    l0 = l0 * a0 + ps0;
                    l1 = l1 * a1 + ps1;
                    #pragma unroll
                    for (int nt = 0; nt < 8; nt++) {
                        o[nt][0] *= a0; o[nt][1] *= a0;
                        o[nt][2] *= a1; o[nt][3] *= a1;
                    }

                    // ---- O += Ph Vh ----
                    {
                        const int vrl = (lane & 7) + 8 * ((lane >> 3) & 1);
                        const int vcb = 8 * (lane >> 4);
                        #pragma unroll
                        for (int kc = 0; kc < 4; kc++) {
                            uint32_t vh[8][2];
                            #pragma unroll
                            for (int dp = 0; dp < 4; dp++) {
                                const uint32_t off =
                                    (uint32_t)(kc * 16 + vrl) * APB + (dp * 16 + vcb) * 2;
                                LDSM_X4T(vh[2*dp][0], vh[2*dp][1], vh[2*dp+1][0], vh[2*dp+1][1],
                                         sVhT + off);
                            }
                            #pragma unroll
                            for (int nt = 0; nt < 8; nt++)
                                MMA_F16(o[nt], pah[kc], vh[nt]);
                        }
                    }
                }
                __syncthreads();
            }

            l0 += __shfl_xor_sync(0xffffffffu, l0, 1);
            l0 += __shfl_xor_sync(0xffffffffu, l0, 2);
            l1 += __shfl_xor_sync(0xffffffffu, l1, 1);
            l1 += __shfl_xor_sync(0xffffffffu, l1, 2);
            const float i0 = 1.f / l0, i1 = 1.f / l1;

            if (phase == 0) {
                #pragma unroll
                for (int nt = 0; nt < 8; nt++) {
                    const int c = nt * 8 + ccol;
                    sO[rloc * 68 + c]           = o[nt][0] * i0;
                    sO[rloc * 68 + c + 1]       = o[nt][1] * i0;
                    sO[(rloc + 8) * 68 + c]     = o[nt][2] * i1;
                    sO[(rloc + 8) * 68 + c + 1] = o[nt][3] * i1;
                }
            } else {
                const int r0 = q0 + wid * 16 + crow;
                __half* yh0 = Yh + ((size_t)b * Tt + r0) * Cc + h * Dd;
                __half* yh1 = yh0 + 8 * Cc;
                #pragma unroll
                for (int nt = 0; nt < 8; nt++) {
                    const int c = nt * 8 + ccol;
                    float vx0 = sO[rloc * 68 + c]           + o[nt][0] * i0;
                    float vy0 = sO[rloc * 68 + c + 1]       + o[nt][1] * i0;
                    float vx1 = sO[(rloc + 8) * 68 + c]     + o[nt][2] * i1;
                    float vy1 = sO[(rloc + 8) * 68 + c + 1] + o[nt][3] * i1;
                    __half2 h0 = __float22half2_rn(make_float2(vx0, vy0));
                    __half2 h1 = __float22half2_rn(make_float2(vx1, vy1));
                    *(uint32_t*)&yh0[c] = *(uint32_t*)&h0;
                    *(uint32_t*)&yh1[c] = *(uint32_t*)&h1;
                }
            }
        }
        __syncthreads();   // protect sO / sQ / sKV before next work item
    }
}

// ---------------------------------------------------------------------------

extern "C" void kernel_launch(void* const* d_in, const int* in_sizes, int n_in,
                              void* d_out, int out_size)
{
    const float* x     = (const float*)d_in[0];
    const float* cross = (const float*)d_in[1];
    const float* Wk  = (const float*)d_in[2];   const float* bk  = (const float*)d_in[3];
    const float* Wq  = (const float*)d_in[4];   const float* bq  = (const float*)d_in[5];
    const float* Wv  = (const float*)d_in[6];   const float* bv  = (const float*)d_in[7];
    const float* Wck = (const float*)d_in[8];   const float* bck = (const float*)d_in[9];
    const float* Wcq = (const float*)d_in[10];  const float* bcq = (const float*)d_in[11];
    const float* Wcv = (const float*)d_in[12];  const float* bcv = (const float*)d_in[13];
    const float* Wp  = (const float*)d_in[14];  const float* bp  = (const float*)d_in[15];
    float* out = (float*)d_out;

    __half *qkvh, *kvch, *yh;
    cudaGetSymbolAddress((void**)&qkvh, g_qkvh);
    cudaGetSymbolAddress((void**)&kvch, g_kvch);
    cudaGetSymbolAddress((void**)&yh, g_yh);

    // prep: weights transpose + (cvt x, cvt cross, bias concat, counter reset)
    transpose_all_kernel<<<dim3(32, 32, 7), dim3(32, 8)>>>(Wq, Wk, Wv, Wcq, Wck, Wcv, Wp);
    const int ntot = NX + NC + 6144;
    prep_misc_kernel<<<(ntot + 255) / 256, 256>>>(x, cross, bq, bk, bv, bcq, bck, bcv);

    cudaFuncSetAttribute(proj_dual_kernel, cudaFuncAttributeMaxDynamicSharedMemorySize, SM1);
    cudaFuncSetAttribute(out_proj_kernel,  cudaFuncAttributeMaxDynamicSharedMemorySize, SM1);
    cudaFuncSetAttribute(attn_fused_kernel, cudaFuncAttributeMaxDynamicSharedMemorySize, ATT_SMEM);
    const dim3 gblk(256);

    // unified projections: QKV tiles first, cross tiles fill the tail wave
    proj_dual_kernel<<<T1_TILES + T2_TILES, gblk, SM1>>>();

    // persistent fused attention (self causal + cross), 2 CTAs/SM
    attn_fused_kernel<<<296, gblk, ATT_SMEM>>>(qkvh, kvch, yh);

    // output projection
    out_proj_kernel<<<dim3(Cc / 128, (Bb * Tt) / 128), gblk, SM1>>>(bp, out);
}